// round 8
// baseline (speedup 1.0000x reference)
#include <cuda_runtime.h>
#include <cuda_bf16.h>
#include <cstdint>
#include <cstdio>

// ---------------------------------------------------------------------------
// Problem constants
// ---------------------------------------------------------------------------
#define NB 1024
static const int D_TOT = 267696;

// permuted tf32 weight buffer offsets (see wperm_k)
static const int PO_H[19] = {0,1152,3584,6016,8448,10880,13312,15744,20352,30080,
                             39808,49536,59264,68992,87424,126336,165248,204160,243072};
#define WP_TOT 281984

__constant__ int c_PO[19]   = {0,1152,3584,6016,8448,10880,13312,15744,20352,30080,
                               39808,49536,59264,68992,87424,126336,165248,204160,243072};
__constant__ int c_WOFF[19] = {0,432,2736,5040,7344,9648,11952,14256,18864,28080,
                               37296,46512,55728,64944,83376,120240,157104,193968,230832};
__constant__ int c_LCIN[19]  = {3,16,16,16,16,16,16,16,32,32,32,32,32,32,64,64,64,64,64};
__constant__ int c_LICC[19]  = {8,16,16,16,16,16,16,8,16,16,16,16,16,8,16,16,16,16,16};
__constant__ int c_LCOUT[19] = {16,16,16,16,16,16,16,32,32,32,32,32,32,64,64,64,64,64,64};
__constant__ int c_LPITCH[19]= {72,152,152,152,152,152,152,72,152,152,152,152,152,72,152,152,152,152,152};

// ---------------------------------------------------------------------------
// Device scratch
// ---------------------------------------------------------------------------
#define BUF_ELEMS (1024*16*32*32)
__device__ float    g_bufA[BUF_ELEMS];
__device__ float    g_bufB[BUF_ELEMS];
__device__ float    g_bufC[BUF_ELEMS];
__device__ float    g_bufD[BUF_ELEMS];
__device__ float    g_w[267696];       // natural per-layer layout: [oc][ic][3][3]
__device__ uint32_t g_wp[WP_TOT];      // permuted tf32 smem-image weights
__device__ double   g_stats[19*64*2];  // per layer, per channel: sum, sumsq

// ---------------------------------------------------------------------------
// helpers
// ---------------------------------------------------------------------------
__host__ __device__ constexpr int pitchf(int K) {
    int p = K;
    while (!((p % 32) == 8 || (p % 32) == 24)) p++;
    return p;
}
__device__ __forceinline__ uint32_t f2tf32(float v) {
    uint32_t u; asm("cvt.rna.tf32.f32 %0, %1;" : "=r"(u) : "f"(v)); return u;
}
__device__ __forceinline__ void mma_tf32(float c[4],
                                         uint32_t a0, uint32_t a1, uint32_t a2, uint32_t a3,
                                         uint32_t b0, uint32_t b1) {
    asm volatile(
        "mma.sync.aligned.m16n8k8.row.col.f32.tf32.tf32.f32 "
        "{%0,%1,%2,%3}, {%4,%5,%6,%7}, {%8,%9}, {%0,%1,%2,%3};"
        : "+f"(c[0]), "+f"(c[1]), "+f"(c[2]), "+f"(c[3])
        : "r"(a0), "r"(a1), "r"(a2), "r"(a3), "r"(b0), "r"(b1));
}

// ---------------------------------------------------------------------------
__global__ void zstats_k(double* __restrict__ st) {
    int i = blockIdx.x * blockDim.x + threadIdx.x;
    if (i < 19*64*2) st[i] = 0.0;
}

__global__ void wbuild_k(const float* __restrict__ ow, const float* __restrict__ P,
                         const float* __restrict__ npar, float* __restrict__ wt) {
    __shared__ float s_np[40];
    if (threadIdx.x < 40) s_np[threadIdx.x] = npar[threadIdx.x];
    __syncthreads();
    int d = blockIdx.x * blockDim.x + threadIdx.x;
    if (d >= D_TOT) return;
    float a = ow[d];
#pragma unroll
    for (int j = 0; j < 40; j++)
        a = fmaf(s_np[j], P[(size_t)j * D_TOT + d], a);
    wt[d] = a;
}

// Permute weights into the exact smem image the conv consumes.
__global__ void wperm_k(const float* __restrict__ w, uint32_t* __restrict__ wp) {
    int i = blockIdx.x * blockDim.x + threadIdx.x;
    if (i >= WP_TOT) return;
    int l = 18;
    while (l > 0 && i < c_PO[l]) l--;
    const int r     = i - c_PO[l];
    const int CINR  = c_LCIN[l];
    const int ICC   = c_LICC[l];
    const int COUT  = c_LCOUT[l];
    const int PITCH = c_LPITCH[l];
    const int K     = ICC * 9;
    const int NG    = ICC / 8;
    const int cs    = COUT * PITCH;
    const int ch    = r / cs;
    const int r2    = r - ch * cs;
    const int oc    = r2 / PITCH;
    const int pos   = r2 - oc * PITCH;
    float v = 0.f;
    if (pos < K) {
        const int s    = pos >> 3, phys = pos & 7;
        const int u    = (phys & 1) ? (phys >> 1) + 4 : (phys >> 1);
        const int k    = s / NG, icg = s - (s / NG) * NG;
        const int ic   = ch * ICC + icg * 8 + u;
        if (ic < CINR) v = w[c_WOFF[l] + (oc * CINR + ic) * 9 + k];
    }
    wp[i] = f2tf32(v);
}

// ---------------------------------------------------------------------------
// Direct-from-tile tensor-core conv with fused input transform.
//  MT = m16-tiles per warp (1 or 2); positions per CTA = 128*MT.
//  MODE 0: plain input; 1: relu(bn(in)); 2: relu(bn(in)+prev) identity;
//  MODE 3: relu(bn(in)+padded/strided prev).
//  WF: also write the transformed activation to `fused` during staging.
// ---------------------------------------------------------------------------
template<int CINR, int CINP, int COUT, int HIN, int STRIDE, int ICC, int IMGS,
         int MT, int MODE, int CPREV, bool WF>
__global__ void __launch_bounds__(256)
convt_k(const float* __restrict__ in, const uint32_t* __restrict__ wpb,
        float* __restrict__ out, const double* __restrict__ st_in,
        double* __restrict__ st_out, const float* __restrict__ prev,
        float* __restrict__ fused)
{
    constexpr int W     = HIN / STRIDE;
    constexpr int NPOS  = W * W;
    constexpr int PC    = 128 * MT;              // positions per CTA
    constexpr int R     = PC / (W * IMGS);
    constexpr int SPI   = (IMGS == 1) ? (NPOS / PC) : 1;
    constexpr int TH    = (R - 1) * STRIDE + 3;
    constexpr int TW    = HIN + 2;
    constexpr int NG    = ICC / 8;
    constexpr int NCH   = CINP / ICC;
    constexpr int K     = ICC * 9;
    constexpr int PITCH = pitchf(K);
    constexpr int STEPS = K / 8;
    constexpr int NC    = COUT / 8;
    constexpr int TILEW = IMGS * TH * TW * ICC;
    constexpr int PADF  = (MODE == 3) ? (CINR - CPREV) / 2 : 0;

    extern __shared__ float smf[];
    float*    s_sc = smf;
    float*    s_sh = smf + 64;
    uint32_t* s_a  = (uint32_t*)(smf + 128);
    uint32_t* s_b  = s_a + TILEW;

    const int tid = threadIdx.x, wid = tid >> 5, lane = tid & 31;
    const int g = lane >> 2, t = lane & 3;

    const int img0 = (IMGS == 1) ? (blockIdx.x / SPI) : blockIdx.x * IMGS;
    const int r0   = (IMGS == 1) ? (blockIdx.x % SPI) * R : 0;

    if (MODE >= 1 && tid < CINR) {
        const double cnt = 1024.0 * HIN * HIN;
        double mm = st_in[tid*2]   / cnt;
        double vv = st_in[tid*2+1] / cnt - mm * mm;
        float rs = rsqrtf((float)vv + 1e-5f);
        s_sc[tid] = rs;
        s_sh[tid] = (float)(-mm) * rs;
    }
    if (MODE >= 1) __syncthreads();

    // row-base word offsets into the tile (rows g, g+8, ... per m16 tile)
    int basew[2 * MT];
#pragma unroll
    for (int i = 0; i < 2 * MT; i++) {
        const int p   = wid * (16 * MT) + i * 8 + g;
        const int img = p / (R * W);
        const int rem = p - img * (R * W);
        const int y   = rem / W, x = rem - (rem / W) * W;
        basew[i] = (((img * TH + y * STRIDE) * NG) * TW + x * STRIDE) * 8 + 2 * t;
    }

    float acc[MT][NC][4];
#pragma unroll
    for (int mt = 0; mt < MT; mt++)
#pragma unroll
        for (int nc = 0; nc < NC; nc++)
#pragma unroll
            for (int i = 0; i < 4; i++) acc[mt][nc][i] = 0.f;

    for (int ch = 0; ch < NCH; ch++) {
        const int ic0 = ch * ICC;
        __syncthreads();

        // ---- stage input tile (transform fused in, STS.128) ----
        for (int idx = tid; idx < IMGS * TH * TW; idx += 256) {
            const int img = idx / (TH * TW);
            const int rr  = idx - img * (TH * TW);
            const int ty  = rr / TW, tx = rr - (rr / TW) * TW;
            const int yi  = r0 * STRIDE - 1 + ty;
            const int xi  = tx - 1;
            const bool ok = (unsigned)yi < (unsigned)HIN && (unsigned)xi < (unsigned)HIN;
            const int  n  = img0 + img;
            const float* gb = in + ((size_t)n * CINR + ic0) * HIN * HIN + yi * HIN + xi;
            const float* pv = nullptr;
            if (MODE == 2)
                pv = prev + ((size_t)n * CPREV) * HIN * HIN + yi * HIN + xi;
            if (MODE == 3)
                pv = prev + ((size_t)n * CPREV) * (4 * HIN * HIN)
                          + (2 * yi) * (2 * HIN) + 2 * xi;
            float* fb = nullptr;
            if (WF) fb = fused + ((size_t)n * CINR) * HIN * HIN + yi * HIN + xi;

            uint32_t* dst = s_a + ((img * TH + ty) * NG) * (TW * 8) + tx * 8;
#pragma unroll
            for (int icg = 0; icg < NG; icg++) {
                uint32_t wb8[8];
#pragma unroll
                for (int j = 0; j < 4; j++) {
                    const int ia = icg * 8 + j, ib = ia + 4;
                    float va = 0.f, vb = 0.f;
                    if (ok) {
#pragma unroll
                        for (int hh = 0; hh < 2; hh++) {
                            const int ii = hh ? ib : ia;
                            const int ic = ic0 + ii;
                            float v = 0.f;
                            if (CINR == CINP || ic < CINR) {
                                v = __ldg(gb + ii * HIN * HIN);
                                if (MODE >= 1) v = fmaf(v, s_sc[ic], s_sh[ic]);
                                if (MODE == 2) v += __ldg(pv + ic * HIN * HIN);
                                if (MODE == 3) {
                                    const int pc = ic - PADF;
                                    if (pc >= 0 && pc < CPREV)
                                        v += __ldg(pv + pc * (4 * HIN * HIN));
                                }
                                if (MODE >= 1) v = fmaxf(v, 0.f);
                                if (WF) fb[(size_t)ic * HIN * HIN] = v;
                            }
                            if (hh) vb = v; else va = v;
                        }
                    }
                    wb8[2*j]     = f2tf32(va);
                    wb8[2*j + 1] = f2tf32(vb);
                }
                uint4* d4 = (uint4*)(dst + icg * (TW * 8));
                d4[0] = make_uint4(wb8[0], wb8[1], wb8[2], wb8[3]);
                d4[1] = make_uint4(wb8[4], wb8[5], wb8[6], wb8[7]);
            }
        }

        // ---- stage B: plain vector copy of pre-permuted tf32 weights ----
        {
            const uint4* wb = (const uint4*)(wpb + ch * (COUT * PITCH));
            uint4* sb4 = (uint4*)s_b;
#pragma unroll 4
            for (int idx = tid; idx < COUT * PITCH / 4; idx += 256)
                sb4[idx] = wb[idx];
        }
        __syncthreads();

        // ---- MMA over STEPS k-slices ----
#pragma unroll
        for (int s = 0; s < STEPS; s++) {
            const int k   = s / NG;
            const int icg = s - k * NG;
            const int ky  = k / 3, kx = k - (k / 3) * 3;
            const int off = ((ky * NG + icg) * TW + kx) * 8;
            uint2 Af[2 * MT];
#pragma unroll
            for (int i = 0; i < 2 * MT; i++)
                Af[i] = *(const uint2*)(s_a + basew[i] + off);
#pragma unroll
            for (int nc = 0; nc < NC; nc++) {
                uint2 B = *(const uint2*)(s_b + (nc * 8 + g) * PITCH + s * 8 + 2 * t);
#pragma unroll
                for (int mt = 0; mt < MT; mt++)
                    mma_tf32(acc[mt][nc], Af[2*mt].x, Af[2*mt+1].x,
                             Af[2*mt].y, Af[2*mt+1].y, B.x, B.y);
            }
        }
    }

    __syncthreads();   // mainloop smem regions free from here
    float* s_st  = smf + 128;
    float* s_red = s_st + COUT * PC;   // [8 warps][COUT][2]

    // ---- BN stats straight from accumulators ----
#pragma unroll
    for (int nc = 0; nc < NC; nc++) {
        float s0 = 0.f, s1 = 0.f, q0 = 0.f, q1 = 0.f;
#pragma unroll
        for (int mt = 0; mt < MT; mt++) {
            s0 += acc[mt][nc][0] + acc[mt][nc][2];
            s1 += acc[mt][nc][1] + acc[mt][nc][3];
            q0 += acc[mt][nc][0]*acc[mt][nc][0] + acc[mt][nc][2]*acc[mt][nc][2];
            q1 += acc[mt][nc][1]*acc[mt][nc][1] + acc[mt][nc][3]*acc[mt][nc][3];
        }
#pragma unroll
        for (int off = 4; off < 32; off <<= 1) {
            s0 += __shfl_xor_sync(0xffffffffu, s0, off);
            s1 += __shfl_xor_sync(0xffffffffu, s1, off);
            q0 += __shfl_xor_sync(0xffffffffu, q0, off);
            q1 += __shfl_xor_sync(0xffffffffu, q1, off);
        }
        if (lane < 4) {
            const int cb = nc * 8 + 2 * lane;
            s_red[(wid * COUT + cb)     * 2 + 0] = s0;
            s_red[(wid * COUT + cb)     * 2 + 1] = q0;
            s_red[(wid * COUT + cb + 1) * 2 + 0] = s1;
            s_red[(wid * COUT + cb + 1) * 2 + 1] = q1;
        }
    }

    // ---- frags -> smem staging [COUT][PC] ----
#pragma unroll
    for (int mt = 0; mt < MT; mt++)
#pragma unroll
        for (int nc = 0; nc < NC; nc++) {
            const int cb = nc * 8 + 2 * t;
            const int p0 = wid * (16 * MT) + mt * 16 + g;
            s_st[(cb + 0) * PC + p0]     = acc[mt][nc][0];
            s_st[(cb + 1) * PC + p0]     = acc[mt][nc][1];
            s_st[(cb + 0) * PC + p0 + 8] = acc[mt][nc][2];
            s_st[(cb + 1) * PC + p0 + 8] = acc[mt][nc][3];
        }
    __syncthreads();

    // coalesced NCHW store
    for (int idx = tid; idx < COUT * PC; idx += 256) {
        const int c   = idx / PC;
        const int lp  = idx - c * PC;
        const int img = lp / (R * W);
        const int rem = lp - img * (R * W);
        const int y   = r0 + rem / W;
        const int x   = rem - (rem / W) * W;
        out[((size_t)(img0 + img) * COUT + c) * NPOS + y * W + x] = s_st[c * PC + lp];
    }

    if (tid < COUT) {
        float s = 0.f, q = 0.f;
#pragma unroll
        for (int w8 = 0; w8 < 8; w8++) {
            s += s_red[(w8 * COUT + tid) * 2 + 0];
            q += s_red[(w8 * COUT + tid) * 2 + 1];
        }
        atomicAdd(&st_out[tid * 2 + 0], (double)s);
        atomicAdd(&st_out[tid * 2 + 1], (double)q);
    }
}

// ---------------------------------------------------------------------------
// Fused final residual + global average pool (8x8) + FC 64->10
// ---------------------------------------------------------------------------
__global__ void __launch_bounds__(64)
poolfc_k(const float* __restrict__ h2, const double* __restrict__ st,
         const float* __restrict__ prev, const float* __restrict__ Wfc,
         const float* __restrict__ bfc, float* __restrict__ out)
{
    __shared__ float pooled[64];
    const int n = blockIdx.x, t = threadIdx.x;
    const double cnt = 1024.0 * 64.0;
    double m = st[t*2] / cnt;
    double v = st[t*2+1] / cnt - m * m;
    const float sc = rsqrtf((float)v + 1e-5f);
    const float sh = (float)(-m) * sc;
    const float* hp = h2   + (size_t)n * 64 * 64 + t * 64;
    const float* pp = prev + (size_t)n * 64 * 64 + t * 64;
    float s = 0.f;
#pragma unroll
    for (int i = 0; i < 64; i++)
        s += fmaxf(fmaf(hp[i], sc, sh) + pp[i], 0.f);
    pooled[t] = s * (1.f / 64.f);
    __syncthreads();
    if (t < 10) {
        float a = bfc[t];
#pragma unroll
        for (int c = 0; c < 64; c++) a = fmaf(Wfc[t * 64 + c], pooled[c], a);
        out[n * 10 + t] = a;
    }
}

// ---------------------------------------------------------------------------
// Host-side smem size (mirror of kernel constants)
// ---------------------------------------------------------------------------
static constexpr int cm2(int CINP, int COUT, int HIN, int STRIDE, int ICC,
                         int IMGS, int MT) {
    int W  = HIN / STRIDE;
    int PC = 128 * MT;
    int R  = PC / (W * IMGS);
    int TH = (R - 1) * STRIDE + 3;
    int TW = HIN + 2;
    int K  = ICC * 9;
    int P  = pitchf(K);
    int tile = IMGS * TH * TW * ICC;
    int p1 = tile + COUT * P;
    int p2 = COUT * PC + 16 * COUT;
    int m  = (p1 > p2) ? p1 : p2;
    return (128 + m) * 4;
}

extern "C" void kernel_launch(void* const* d_in, const int* in_sizes, int n_in,
                              void* d_out, int out_size)
{
    (void)in_sizes; (void)n_in; (void)out_size;
    const float* x   = (const float*)d_in[0];
    const float* ow  = (const float*)d_in[1];
    const float* P   = (const float*)d_in[2];
    const float* npar= (const float*)d_in[3];
    const float* Wfc = (const float*)d_in[4];
    const float* bfc = (const float*)d_in[5];
    float* y = (float*)d_out;

    float *A, *B, *C, *D, *w; uint32_t* wp; double* st;
    cudaGetSymbolAddress((void**)&A,  g_bufA);
    cudaGetSymbolAddress((void**)&B,  g_bufB);
    cudaGetSymbolAddress((void**)&C,  g_bufC);
    cudaGetSymbolAddress((void**)&D,  g_bufD);
    cudaGetSymbolAddress((void**)&w,  g_w);
    cudaGetSymbolAddress((void**)&wp, g_wp);
    cudaGetSymbolAddress((void**)&st, g_stats);

    #define SETSM(FN, CINP_, COUT_, HIN_, STRIDE_, ICC_, IMGS_, MT_) \
        cudaFuncSetAttribute(FN, cudaFuncAttributeMaxDynamicSharedMemorySize, \
                             cm2(CINP_, COUT_, HIN_, STRIDE_, ICC_, IMGS_, MT_))

    auto I0  = convt_k< 3, 8,16,32,1, 8,1,2,0, 0,false>; SETSM(I0,  8,16,32,1, 8,1,2);
    auto I1  = convt_k<16,16,16,32,1,16,1,2,1, 0,true >; SETSM(I1, 16,16,32,1,16,1,2);
    auto I2  = convt_k<16,16,16,32,1,16,1,2,1, 0,false>; SETSM(I2, 16,16,32,1,16,1,2);
    auto I3  = convt_k<16,16,16,32,1,16,1,2,2,16,true >; SETSM(I3, 16,16,32,1,16,1,2);
    auto I4  = convt_k<16,16,32,32,2, 8,1,2,2,16,true >; SETSM(I4, 16,32,32,2, 8,1,2);
    auto I5  = convt_k<32,32,32,16,1,16,1,2,1, 0,false>; SETSM(I5, 32,32,16,1,16,1,2);
    auto I6  = convt_k<32,32,32,16,1,16,1,2,3,16,true >; SETSM(I6, 32,32,16,1,16,1,2);
    auto I7  = convt_k<32,32,32,16,1,16,1,2,2,32,true >; SETSM(I7, 32,32,16,1,16,1,2);
    auto I8  = convt_k<32,32,64,16,2, 8,2,1,2,32,true >; SETSM(I8, 32,64,16,2, 8,2,1);
    auto I9  = convt_k<64,64,64, 8,1,16,2,1,1, 0,false>; SETSM(I9, 64,64, 8,1,16,2,1);
    auto I10 = convt_k<64,64,64, 8,1,16,2,1,3,32,true >; SETSM(I10,64,64, 8,1,16,2,1);
    auto I11 = convt_k<64,64,64, 8,1,16,2,1,2,64,true >; SETSM(I11,64,64, 8,1,16,2,1);
    #undef SETSM

    auto ST = [&](int l) { return st + l * 128; };
    auto WL = [&](int l) { return wp + PO_H[l]; };

    zstats_k<<<(19*64*2 + 255)/256, 256>>>(st);
    wbuild_k<<<(D_TOT + 255)/256, 256>>>(ow, P, npar, w);
    wperm_k<<<(WP_TOT + 255)/256, 256>>>(w, wp);

    const int S1 = cm2( 8,16,32,1, 8,1,2);
    const int S2 = cm2(16,16,32,1,16,1,2);
    const int S3 = cm2(16,32,32,2, 8,1,2);
    const int S4 = cm2(32,32,16,1,16,1,2);
    const int S5 = cm2(32,64,16,2, 8,2,1);
    const int S6 = cm2(64,64, 8,1,16,2,1);

    // layer 0
    I0 <<<4096,256,S1>>>(x, WL(0), A, nullptr, ST(0), nullptr, nullptr);
    // block 1
    I1 <<<4096,256,S2>>>(A, WL(1), B, ST(0),  ST(1), nullptr, C);
    I2 <<<4096,256,S2>>>(B, WL(2), A, ST(1),  ST(2), nullptr, nullptr);
    // block 2
    I3 <<<4096,256,S2>>>(A, WL(3), B, ST(2),  ST(3), C, D);
    I2 <<<4096,256,S2>>>(B, WL(4), C, ST(3),  ST(4), nullptr, nullptr);
    // block 3
    I3 <<<4096,256,S2>>>(C, WL(5), B, ST(4),  ST(5), D, A);
    I2 <<<4096,256,S2>>>(B, WL(6), D, ST(5),  ST(6), nullptr, nullptr);
    // block 4 (16->32, stride 2)
    I4 <<<1024,256,S3>>>(D, WL(7), B, ST(6),  ST(7), A, C);
    I5 <<<1024,256,S4>>>(B, WL(8), A, ST(7),  ST(8), nullptr, nullptr);
    // block 5 (MODE3 pad shortcut, prev 16ch@32)
    I6 <<<1024,256,S4>>>(A, WL(9), B, ST(8),  ST(9), C, D);
    I5 <<<1024,256,S4>>>(B, WL(10),C, ST(9),  ST(10),nullptr, nullptr);
    // block 6
    I7 <<<1024,256,S4>>>(C, WL(11),B, ST(10), ST(11),D, A);
    I5 <<<1024,256,S4>>>(B, WL(12),D, ST(11), ST(12),nullptr, nullptr);
    // block 7 (32->64, stride 2)  -- MT=1, grid 512
    I8 <<< 512,256,S5>>>(D, WL(13),B, ST(12), ST(13),A, C);
    I9 <<< 512,256,S6>>>(B, WL(14),A, ST(13), ST(14),nullptr, nullptr);
    // block 8 (MODE3 pad shortcut, prev 32ch@16)
    I10<<< 512,256,S6>>>(A, WL(15),B, ST(14), ST(15),C, D);
    I9 <<< 512,256,S6>>>(B, WL(16),C, ST(15), ST(16),nullptr, nullptr);
    // block 9
    I11<<< 512,256,S6>>>(C, WL(17),B, ST(16), ST(17),D, A);
    I9 <<< 512,256,S6>>>(B, WL(18),D, ST(17), ST(18),nullptr, nullptr);
    // fused final residual + pool + fc
    poolfc_k<<<NB,64>>>(D, ST(18), A, Wfc, bfc, y);
}

// round 9
// speedup vs baseline: 1.0850x; 1.0850x over previous
#include <cuda_runtime.h>
#include <cuda_bf16.h>
#include <cstdint>
#include <cstdio>

// ---------------------------------------------------------------------------
// Problem constants
// ---------------------------------------------------------------------------
#define NB 1024
static const int D_TOT = 267696;

// permuted tf32 weight buffer offsets (see wperm_k); ICC per layer:
// {8,16,16,16,16,16,16,8,8,8,8,8,8,8,16,16,16,16,16}
static const int PO_H[19] = {0,1152,3584,6016,8448,10880,13312,15744,20352,29568,
                             38784,48000,57216,66432,84864,123776,162688,201600,240512};
#define WP_TOT 279424

__constant__ int c_PO[19]   = {0,1152,3584,6016,8448,10880,13312,15744,20352,29568,
                               38784,48000,57216,66432,84864,123776,162688,201600,240512};
__constant__ int c_WOFF[19] = {0,432,2736,5040,7344,9648,11952,14256,18864,28080,
                               37296,46512,55728,64944,83376,120240,157104,193968,230832};
__constant__ int c_LCIN[19]  = {3,16,16,16,16,16,16,16,32,32,32,32,32,32,64,64,64,64,64};
__constant__ int c_LICC[19]  = {8,16,16,16,16,16,16,8,8,8,8,8,8,8,16,16,16,16,16};
__constant__ int c_LCOUT[19] = {16,16,16,16,16,16,16,32,32,32,32,32,32,64,64,64,64,64,64};
__constant__ int c_LPITCH[19]= {72,152,152,152,152,152,152,72,72,72,72,72,72,72,152,152,152,152,152};

// ---------------------------------------------------------------------------
// Device scratch
// ---------------------------------------------------------------------------
#define BUF_ELEMS (1024*16*32*32)
__device__ float    g_bufA[BUF_ELEMS];
__device__ float    g_bufB[BUF_ELEMS];
__device__ float    g_bufC[BUF_ELEMS];
__device__ float    g_bufD[BUF_ELEMS];
__device__ float    g_w[267696];       // natural per-layer layout: [oc][ic][3][3]
__device__ uint32_t g_wp[WP_TOT];      // permuted tf32 smem-image weights
__device__ double   g_stats[19*64*2];  // per layer, per channel: sum, sumsq

// ---------------------------------------------------------------------------
// helpers
// ---------------------------------------------------------------------------
__host__ __device__ constexpr int pitchf(int K) {
    int p = K;
    while (!((p % 32) == 8 || (p % 32) == 24)) p++;
    return p;
}
__device__ __forceinline__ uint32_t f2tf32(float v) {
    uint32_t u; asm("cvt.rna.tf32.f32 %0, %1;" : "=r"(u) : "f"(v)); return u;
}
__device__ __forceinline__ void mma_tf32(float c[4],
                                         uint32_t a0, uint32_t a1, uint32_t a2, uint32_t a3,
                                         uint32_t b0, uint32_t b1) {
    asm volatile(
        "mma.sync.aligned.m16n8k8.row.col.f32.tf32.tf32.f32 "
        "{%0,%1,%2,%3}, {%4,%5,%6,%7}, {%8,%9}, {%0,%1,%2,%3};"
        : "+f"(c[0]), "+f"(c[1]), "+f"(c[2]), "+f"(c[3])
        : "r"(a0), "r"(a1), "r"(a2), "r"(a3), "r"(b0), "r"(b1));
}

// ---------------------------------------------------------------------------
__global__ void zstats_k(double* __restrict__ st) {
    int i = blockIdx.x * blockDim.x + threadIdx.x;
    if (i < 19*64*2) st[i] = 0.0;
}

__global__ void wbuild_k(const float* __restrict__ ow, const float* __restrict__ P,
                         const float* __restrict__ npar, float* __restrict__ wt) {
    __shared__ float s_np[40];
    if (threadIdx.x < 40) s_np[threadIdx.x] = npar[threadIdx.x];
    __syncthreads();
    int d = blockIdx.x * blockDim.x + threadIdx.x;
    if (d >= D_TOT) return;
    float a = ow[d];
#pragma unroll
    for (int j = 0; j < 40; j++)
        a = fmaf(s_np[j], P[(size_t)j * D_TOT + d], a);
    wt[d] = a;
}

// Permute weights into the exact smem image the conv consumes.
__global__ void wperm_k(const float* __restrict__ w, uint32_t* __restrict__ wp) {
    int i = blockIdx.x * blockDim.x + threadIdx.x;
    if (i >= WP_TOT) return;
    int l = 18;
    while (l > 0 && i < c_PO[l]) l--;
    const int r     = i - c_PO[l];
    const int CINR  = c_LCIN[l];
    const int ICC   = c_LICC[l];
    const int COUT  = c_LCOUT[l];
    const int PITCH = c_LPITCH[l];
    const int K     = ICC * 9;
    const int NG    = ICC / 8;
    const int cs    = COUT * PITCH;
    const int ch    = r / cs;
    const int r2    = r - ch * cs;
    const int oc    = r2 / PITCH;
    const int pos   = r2 - oc * PITCH;
    float v = 0.f;
    if (pos < K) {
        const int s    = pos >> 3, phys = pos & 7;
        const int u    = (phys & 1) ? (phys >> 1) + 4 : (phys >> 1);
        const int k    = s / NG, icg = s - (s / NG) * NG;
        const int ic   = ch * ICC + icg * 8 + u;
        if (ic < CINR) v = w[c_WOFF[l] + (oc * CINR + ic) * 9 + k];
    }
    wp[i] = f2tf32(v);
}

// ---------------------------------------------------------------------------
// Direct-from-tile tensor-core conv with fused input transform.
//  MT = m16-tiles per warp; positions per CTA = 128*MT. MINB = min blocks/SM.
//  MODE 0: plain input; 1: relu(bn(in)); 2: relu(bn(in)+prev) identity;
//  MODE 3: relu(bn(in)+padded/strided prev).
//  WF: also write the transformed activation to `fused` during staging.
// ---------------------------------------------------------------------------
template<int CINR, int CINP, int COUT, int HIN, int STRIDE, int ICC, int IMGS,
         int MT, int MODE, int CPREV, bool WF, int MINB>
__global__ void __launch_bounds__(256, MINB)
convt_k(const float* __restrict__ in, const uint32_t* __restrict__ wpb,
        float* __restrict__ out, const double* __restrict__ st_in,
        double* __restrict__ st_out, const float* __restrict__ prev,
        float* __restrict__ fused)
{
    constexpr int W     = HIN / STRIDE;
    constexpr int NPOS  = W * W;
    constexpr int PC    = 128 * MT;              // positions per CTA
    constexpr int R     = PC / (W * IMGS);
    constexpr int SPI   = (IMGS == 1) ? (NPOS / PC) : 1;
    constexpr int TH    = (R - 1) * STRIDE + 3;
    constexpr int TW    = HIN + 2;
    constexpr int NG    = ICC / 8;
    constexpr int NCH   = CINP / ICC;
    constexpr int K     = ICC * 9;
    constexpr int PITCH = pitchf(K);
    constexpr int STEPS = K / 8;
    constexpr int NC    = COUT / 8;
    constexpr int TILEW = IMGS * TH * TW * ICC;
    constexpr int PADF  = (MODE == 3) ? (CINR - CPREV) / 2 : 0;

    extern __shared__ float smf[];
    float*    s_sc = smf;
    float*    s_sh = smf + 64;
    uint32_t* s_a  = (uint32_t*)(smf + 128);
    uint32_t* s_b  = s_a + TILEW;

    const int tid = threadIdx.x, wid = tid >> 5, lane = tid & 31;
    const int g = lane >> 2, t = lane & 3;

    const int img0 = (IMGS == 1) ? (blockIdx.x / SPI) : blockIdx.x * IMGS;
    const int r0   = (IMGS == 1) ? (blockIdx.x % SPI) * R : 0;

    if (MODE >= 1 && tid < CINR) {
        const double cnt = 1024.0 * HIN * HIN;
        double mm = st_in[tid*2]   / cnt;
        double vv = st_in[tid*2+1] / cnt - mm * mm;
        float rs = rsqrtf((float)vv + 1e-5f);
        s_sc[tid] = rs;
        s_sh[tid] = (float)(-mm) * rs;
    }
    if (MODE >= 1) __syncthreads();

    // row-base word offsets into the tile (rows g, g+8, ... per m16 tile)
    int basew[2 * MT];
#pragma unroll
    for (int i = 0; i < 2 * MT; i++) {
        const int p   = wid * (16 * MT) + i * 8 + g;
        const int img = p / (R * W);
        const int rem = p - img * (R * W);
        const int y   = rem / W, x = rem - (rem / W) * W;
        basew[i] = (((img * TH + y * STRIDE) * NG) * TW + x * STRIDE) * 8 + 2 * t;
    }

    float acc[MT][NC][4];
#pragma unroll
    for (int mt = 0; mt < MT; mt++)
#pragma unroll
        for (int nc = 0; nc < NC; nc++)
#pragma unroll
            for (int i = 0; i < 4; i++) acc[mt][nc][i] = 0.f;

    for (int ch = 0; ch < NCH; ch++) {
        const int ic0 = ch * ICC;
        __syncthreads();

        // ---- stage input tile (transform fused in, STS.128) ----
        for (int idx = tid; idx < IMGS * TH * TW; idx += 256) {
            const int img = idx / (TH * TW);
            const int rr  = idx - img * (TH * TW);
            const int ty  = rr / TW, tx = rr - (rr / TW) * TW;
            const int yi  = r0 * STRIDE - 1 + ty;
            const int xi  = tx - 1;
            const bool ok = (unsigned)yi < (unsigned)HIN && (unsigned)xi < (unsigned)HIN;
            const int  n  = img0 + img;
            const float* gb = in + ((size_t)n * CINR + ic0) * HIN * HIN + yi * HIN + xi;
            const float* pv = nullptr;
            if (MODE == 2)
                pv = prev + ((size_t)n * CPREV) * HIN * HIN + yi * HIN + xi;
            if (MODE == 3)
                pv = prev + ((size_t)n * CPREV) * (4 * HIN * HIN)
                          + (2 * yi) * (2 * HIN) + 2 * xi;
            float* fb = nullptr;
            if (WF) fb = fused + ((size_t)n * CINR) * HIN * HIN + yi * HIN + xi;

            uint32_t* dst = s_a + ((img * TH + ty) * NG) * (TW * 8) + tx * 8;
#pragma unroll
            for (int icg = 0; icg < NG; icg++) {
                uint32_t wb8[8];
#pragma unroll
                for (int j = 0; j < 4; j++) {
                    const int ia = icg * 8 + j, ib = ia + 4;
                    float va = 0.f, vb = 0.f;
                    if (ok) {
#pragma unroll
                        for (int hh = 0; hh < 2; hh++) {
                            const int ii = hh ? ib : ia;
                            const int ic = ic0 + ii;
                            float v = 0.f;
                            if (CINR == CINP || ic < CINR) {
                                v = __ldg(gb + ii * HIN * HIN);
                                if (MODE >= 1) v = fmaf(v, s_sc[ic], s_sh[ic]);
                                if (MODE == 2) v += __ldg(pv + ic * HIN * HIN);
                                if (MODE == 3) {
                                    const int pc = ic - PADF;
                                    if (pc >= 0 && pc < CPREV)
                                        v += __ldg(pv + pc * (4 * HIN * HIN));
                                }
                                if (MODE >= 1) v = fmaxf(v, 0.f);
                                if (WF) fb[(size_t)ic * HIN * HIN] = v;
                            }
                            if (hh) vb = v; else va = v;
                        }
                    }
                    wb8[2*j]     = f2tf32(va);
                    wb8[2*j + 1] = f2tf32(vb);
                }
                uint4* d4 = (uint4*)(dst + icg * (TW * 8));
                d4[0] = make_uint4(wb8[0], wb8[1], wb8[2], wb8[3]);
                d4[1] = make_uint4(wb8[4], wb8[5], wb8[6], wb8[7]);
            }
        }

        // ---- stage B: plain vector copy of pre-permuted tf32 weights ----
        {
            const uint4* wb = (const uint4*)(wpb + ch * (COUT * PITCH));
            uint4* sb4 = (uint4*)s_b;
#pragma unroll 4
            for (int idx = tid; idx < COUT * PITCH / 4; idx += 256)
                sb4[idx] = wb[idx];
        }
        __syncthreads();

        // ---- MMA over STEPS k-slices ----
#pragma unroll
        for (int s = 0; s < STEPS; s++) {
            const int k   = s / NG;
            const int icg = s - k * NG;
            const int ky  = k / 3, kx = k - (k / 3) * 3;
            const int off = ((ky * NG + icg) * TW + kx) * 8;
            uint2 Af[2 * MT];
#pragma unroll
            for (int i = 0; i < 2 * MT; i++)
                Af[i] = *(const uint2*)(s_a + basew[i] + off);
#pragma unroll
            for (int nc = 0; nc < NC; nc++) {
                uint2 B = *(const uint2*)(s_b + (nc * 8 + g) * PITCH + s * 8 + 2 * t);
#pragma unroll
                for (int mt = 0; mt < MT; mt++)
                    mma_tf32(acc[mt][nc], Af[2*mt].x, Af[2*mt+1].x,
                             Af[2*mt].y, Af[2*mt+1].y, B.x, B.y);
            }
        }
    }

    __syncthreads();   // mainloop smem regions free from here
    float* s_st  = smf + 128;
    float* s_red = s_st + COUT * PC;   // [8 warps][COUT][2]

    // ---- BN stats straight from accumulators ----
#pragma unroll
    for (int nc = 0; nc < NC; nc++) {
        float s0 = 0.f, s1 = 0.f, q0 = 0.f, q1 = 0.f;
#pragma unroll
        for (int mt = 0; mt < MT; mt++) {
            s0 += acc[mt][nc][0] + acc[mt][nc][2];
            s1 += acc[mt][nc][1] + acc[mt][nc][3];
            q0 += acc[mt][nc][0]*acc[mt][nc][0] + acc[mt][nc][2]*acc[mt][nc][2];
            q1 += acc[mt][nc][1]*acc[mt][nc][1] + acc[mt][nc][3]*acc[mt][nc][3];
        }
#pragma unroll
        for (int off = 4; off < 32; off <<= 1) {
            s0 += __shfl_xor_sync(0xffffffffu, s0, off);
            s1 += __shfl_xor_sync(0xffffffffu, s1, off);
            q0 += __shfl_xor_sync(0xffffffffu, q0, off);
            q1 += __shfl_xor_sync(0xffffffffu, q1, off);
        }
        if (lane < 4) {
            const int cb = nc * 8 + 2 * lane;
            s_red[(wid * COUT + cb)     * 2 + 0] = s0;
            s_red[(wid * COUT + cb)     * 2 + 1] = q0;
            s_red[(wid * COUT + cb + 1) * 2 + 0] = s1;
            s_red[(wid * COUT + cb + 1) * 2 + 1] = q1;
        }
    }

    // ---- frags -> smem staging [COUT][PC] ----
#pragma unroll
    for (int mt = 0; mt < MT; mt++)
#pragma unroll
        for (int nc = 0; nc < NC; nc++) {
            const int cb = nc * 8 + 2 * t;
            const int p0 = wid * (16 * MT) + mt * 16 + g;
            s_st[(cb + 0) * PC + p0]     = acc[mt][nc][0];
            s_st[(cb + 1) * PC + p0]     = acc[mt][nc][1];
            s_st[(cb + 0) * PC + p0 + 8] = acc[mt][nc][2];
            s_st[(cb + 1) * PC + p0 + 8] = acc[mt][nc][3];
        }
    __syncthreads();

    // coalesced NCHW store
    for (int idx = tid; idx < COUT * PC; idx += 256) {
        const int c   = idx / PC;
        const int lp  = idx - c * PC;
        const int img = lp / (R * W);
        const int rem = lp - img * (R * W);
        const int y   = r0 + rem / W;
        const int x   = rem - (rem / W) * W;
        out[((size_t)(img0 + img) * COUT + c) * NPOS + y * W + x] = s_st[c * PC + lp];
    }

    if (tid < COUT) {
        float s = 0.f, q = 0.f;
#pragma unroll
        for (int w8 = 0; w8 < 8; w8++) {
            s += s_red[(w8 * COUT + tid) * 2 + 0];
            q += s_red[(w8 * COUT + tid) * 2 + 1];
        }
        atomicAdd(&st_out[tid * 2 + 0], (double)s);
        atomicAdd(&st_out[tid * 2 + 1], (double)q);
    }
}

// ---------------------------------------------------------------------------
// Fused final residual + global average pool (8x8) + FC 64->10
// ---------------------------------------------------------------------------
__global__ void __launch_bounds__(64)
poolfc_k(const float* __restrict__ h2, const double* __restrict__ st,
         const float* __restrict__ prev, const float* __restrict__ Wfc,
         const float* __restrict__ bfc, float* __restrict__ out)
{
    __shared__ float pooled[64];
    const int n = blockIdx.x, t = threadIdx.x;
    const double cnt = 1024.0 * 64.0;
    double m = st[t*2] / cnt;
    double v = st[t*2+1] / cnt - m * m;
    const float sc = rsqrtf((float)v + 1e-5f);
    const float sh = (float)(-m) * sc;
    const float* hp = h2   + (size_t)n * 64 * 64 + t * 64;
    const float* pp = prev + (size_t)n * 64 * 64 + t * 64;
    float s = 0.f;
#pragma unroll
    for (int i = 0; i < 64; i++)
        s += fmaxf(fmaf(hp[i], sc, sh) + pp[i], 0.f);
    pooled[t] = s * (1.f / 64.f);
    __syncthreads();
    if (t < 10) {
        float a = bfc[t];
#pragma unroll
        for (int c = 0; c < 64; c++) a = fmaf(Wfc[t * 64 + c], pooled[c], a);
        out[n * 10 + t] = a;
    }
}

// ---------------------------------------------------------------------------
// Host-side smem size (mirror of kernel constants)
// ---------------------------------------------------------------------------
static constexpr int cm2(int CINP, int COUT, int HIN, int STRIDE, int ICC,
                         int IMGS, int MT) {
    int W  = HIN / STRIDE;
    int PC = 128 * MT;
    int R  = PC / (W * IMGS);
    int TH = (R - 1) * STRIDE + 3;
    int TW = HIN + 2;
    int K  = ICC * 9;
    int P  = pitchf(K);
    int tile = IMGS * TH * TW * ICC;
    int p1 = tile + COUT * P;
    int p2 = COUT * PC + 16 * COUT;
    int m  = (p1 > p2) ? p1 : p2;
    return (128 + m) * 4;
}

extern "C" void kernel_launch(void* const* d_in, const int* in_sizes, int n_in,
                              void* d_out, int out_size)
{
    (void)in_sizes; (void)n_in; (void)out_size;
    const float* x   = (const float*)d_in[0];
    const float* ow  = (const float*)d_in[1];
    const float* P   = (const float*)d_in[2];
    const float* npar= (const float*)d_in[3];
    const float* Wfc = (const float*)d_in[4];
    const float* bfc = (const float*)d_in[5];
    float* y = (float*)d_out;

    float *A, *B, *C, *D, *w; uint32_t* wp; double* st;
    cudaGetSymbolAddress((void**)&A,  g_bufA);
    cudaGetSymbolAddress((void**)&B,  g_bufB);
    cudaGetSymbolAddress((void**)&C,  g_bufC);
    cudaGetSymbolAddress((void**)&D,  g_bufD);
    cudaGetSymbolAddress((void**)&w,  g_w);
    cudaGetSymbolAddress((void**)&wp, g_wp);
    cudaGetSymbolAddress((void**)&st, g_stats);

    #define SETSM(FN, CINP_, COUT_, HIN_, STRIDE_, ICC_, IMGS_, MT_) \
        cudaFuncSetAttribute(FN, cudaFuncAttributeMaxDynamicSharedMemorySize, \
                             cm2(CINP_, COUT_, HIN_, STRIDE_, ICC_, IMGS_, MT_))

    // 16-out/16-in variants: MINB=5 (62% occ); 32-out: MINB=4; 64-out: MINB=2
    auto I0  = convt_k< 3, 8,16,32,1, 8,1,2,0, 0,false,5>; SETSM(I0,  8,16,32,1, 8,1,2);
    auto I1  = convt_k<16,16,16,32,1,16,1,2,1, 0,true ,5>; SETSM(I1, 16,16,32,1,16,1,2);
    auto I2  = convt_k<16,16,16,32,1,16,1,2,1, 0,false,5>; SETSM(I2, 16,16,32,1,16,1,2);
    auto I3  = convt_k<16,16,16,32,1,16,1,2,2,16,true ,5>; SETSM(I3, 16,16,32,1,16,1,2);
    auto I4  = convt_k<16,16,32,32,2, 8,1,2,2,16,true ,4>; SETSM(I4, 16,32,32,2, 8,1,2);
    auto I5  = convt_k<32,32,32,16,1, 8,1,2,1, 0,false,4>; SETSM(I5, 32,32,16,1, 8,1,2);
    auto I6  = convt_k<32,32,32,16,1, 8,1,2,3,16,true ,4>; SETSM(I6, 32,32,16,1, 8,1,2);
    auto I7  = convt_k<32,32,32,16,1, 8,1,2,2,32,true ,4>; SETSM(I7, 32,32,16,1, 8,1,2);
    auto I8  = convt_k<32,32,64,16,2, 8,4,2,2,32,true ,2>; SETSM(I8, 32,64,16,2, 8,4,2);
    auto I9  = convt_k<64,64,64, 8,1,16,4,2,1, 0,false,2>; SETSM(I9, 64,64, 8,1,16,4,2);
    auto I10 = convt_k<64,64,64, 8,1,16,4,2,3,32,true ,2>; SETSM(I10,64,64, 8,1,16,4,2);
    auto I11 = convt_k<64,64,64, 8,1,16,4,2,2,64,true ,2>; SETSM(I11,64,64, 8,1,16,4,2);
    #undef SETSM

    auto ST = [&](int l) { return st + l * 128; };
    auto WL = [&](int l) { return wp + PO_H[l]; };

    zstats_k<<<(19*64*2 + 255)/256, 256>>>(st);
    wbuild_k<<<(D_TOT + 255)/256, 256>>>(ow, P, npar, w);
    wperm_k<<<(WP_TOT + 255)/256, 256>>>(w, wp);

    const int S1 = cm2( 8,16,32,1, 8,1,2);
    const int S2 = cm2(16,16,32,1,16,1,2);
    const int S3 = cm2(16,32,32,2, 8,1,2);
    const int S4 = cm2(32,32,16,1, 8,1,2);
    const int S5 = cm2(32,64,16,2, 8,4,2);
    const int S6 = cm2(64,64, 8,1,16,4,2);

    // layer 0
    I0 <<<4096,256,S1>>>(x, WL(0), A, nullptr, ST(0), nullptr, nullptr);
    // block 1
    I1 <<<4096,256,S2>>>(A, WL(1), B, ST(0),  ST(1), nullptr, C);
    I2 <<<4096,256,S2>>>(B, WL(2), A, ST(1),  ST(2), nullptr, nullptr);
    // block 2
    I3 <<<4096,256,S2>>>(A, WL(3), B, ST(2),  ST(3), C, D);
    I2 <<<4096,256,S2>>>(B, WL(4), C, ST(3),  ST(4), nullptr, nullptr);
    // block 3
    I3 <<<4096,256,S2>>>(C, WL(5), B, ST(4),  ST(5), D, A);
    I2 <<<4096,256,S2>>>(B, WL(6), D, ST(5),  ST(6), nullptr, nullptr);
    // block 4 (16->32, stride 2)
    I4 <<<1024,256,S3>>>(D, WL(7), B, ST(6),  ST(7), A, C);
    I5 <<<1024,256,S4>>>(B, WL(8), A, ST(7),  ST(8), nullptr, nullptr);
    // block 5 (MODE3 pad shortcut, prev 16ch@32)
    I6 <<<1024,256,S4>>>(A, WL(9), B, ST(8),  ST(9), C, D);
    I5 <<<1024,256,S4>>>(B, WL(10),C, ST(9),  ST(10),nullptr, nullptr);
    // block 6
    I7 <<<1024,256,S4>>>(C, WL(11),B, ST(10), ST(11),D, A);
    I5 <<<1024,256,S4>>>(B, WL(12),D, ST(11), ST(12),nullptr, nullptr);
    // block 7 (32->64, stride 2)
    I8 <<< 256,256,S5>>>(D, WL(13),B, ST(12), ST(13),A, C);
    I9 <<< 256,256,S6>>>(B, WL(14),A, ST(13), ST(14),nullptr, nullptr);
    // block 8 (MODE3 pad shortcut, prev 32ch@16)
    I10<<< 256,256,S6>>>(A, WL(15),B, ST(14), ST(15),C, D);
    I9 <<< 256,256,S6>>>(B, WL(16),C, ST(15), ST(16),nullptr, nullptr);
    // block 9
    I11<<< 256,256,S6>>>(C, WL(17),B, ST(16), ST(17),D, A);
    I9 <<< 256,256,S6>>>(B, WL(18),D, ST(17), ST(18),nullptr, nullptr);
    // fused final residual + pool + fc
    poolfc_k<<<NB,64>>>(D, ST(18), A, Wfc, bfc, y);
}

// round 10
// speedup vs baseline: 1.1247x; 1.0367x over previous
#include <cuda_runtime.h>
#include <cuda_bf16.h>
#include <cstdint>
#include <cstdio>

// ---------------------------------------------------------------------------
// Problem constants
// ---------------------------------------------------------------------------
#define NB 1024
static const int D_TOT = 267696;

// permuted tf32 weight buffer offsets (see wperm_k); ICC per layer:
// {8,16,16,16,16,16,16,8,8,8,8,8,8,8,16,16,16,16,16}
static const int PO_H[19] = {0,1152,3584,6016,8448,10880,13312,15744,20352,29568,
                             38784,48000,57216,66432,84864,123776,162688,201600,240512};
#define WP_TOT 279424

__constant__ int c_PO[19]   = {0,1152,3584,6016,8448,10880,13312,15744,20352,29568,
                               38784,48000,57216,66432,84864,123776,162688,201600,240512};
__constant__ int c_WOFF[19] = {0,432,2736,5040,7344,9648,11952,14256,18864,28080,
                               37296,46512,55728,64944,83376,120240,157104,193968,230832};
__constant__ int c_LCIN[19]  = {3,16,16,16,16,16,16,16,32,32,32,32,32,32,64,64,64,64,64};
__constant__ int c_LICC[19]  = {8,16,16,16,16,16,16,8,8,8,8,8,8,8,16,16,16,16,16};
__constant__ int c_LCOUT[19] = {16,16,16,16,16,16,16,32,32,32,32,32,32,64,64,64,64,64,64};
__constant__ int c_LPITCH[19]= {72,152,152,152,152,152,152,72,72,72,72,72,72,72,152,152,152,152,152};

// ---------------------------------------------------------------------------
// Device scratch
// ---------------------------------------------------------------------------
#define BUF_ELEMS (1024*16*32*32)
__device__ float    g_bufA[BUF_ELEMS];
__device__ float    g_bufB[BUF_ELEMS];
__device__ float    g_bufC[BUF_ELEMS];
__device__ float    g_bufD[BUF_ELEMS];
__device__ float    g_w[267696];       // natural per-layer layout: [oc][ic][3][3]
__device__ uint32_t g_wp[WP_TOT];      // permuted tf32 smem-image weights
__device__ double   g_stats[19*64*2];  // per layer, per channel: sum, sumsq

// ---------------------------------------------------------------------------
// helpers
// ---------------------------------------------------------------------------
__host__ __device__ constexpr int pitchf(int K) {
    int p = K;
    while (!((p % 32) == 8 || (p % 32) == 24)) p++;
    return p;
}
__device__ __forceinline__ uint32_t f2tf32(float v) {
    uint32_t u; asm("cvt.rna.tf32.f32 %0, %1;" : "=r"(u) : "f"(v)); return u;
}
__device__ __forceinline__ void mma_tf32(float c[4],
                                         uint32_t a0, uint32_t a1, uint32_t a2, uint32_t a3,
                                         uint32_t b0, uint32_t b1) {
    asm volatile(
        "mma.sync.aligned.m16n8k8.row.col.f32.tf32.tf32.f32 "
        "{%0,%1,%2,%3}, {%4,%5,%6,%7}, {%8,%9}, {%0,%1,%2,%3};"
        : "+f"(c[0]), "+f"(c[1]), "+f"(c[2]), "+f"(c[3])
        : "r"(a0), "r"(a1), "r"(a2), "r"(a3), "r"(b0), "r"(b1));
}

// ---------------------------------------------------------------------------
__global__ void zstats_k(double* __restrict__ st) {
    int i = blockIdx.x * blockDim.x + threadIdx.x;
    if (i < 19*64*2) st[i] = 0.0;
}

__global__ void wbuild_k(const float* __restrict__ ow, const float* __restrict__ P,
                         const float* __restrict__ npar, float* __restrict__ wt) {
    __shared__ float s_np[40];
    if (threadIdx.x < 40) s_np[threadIdx.x] = npar[threadIdx.x];
    __syncthreads();
    int d = blockIdx.x * blockDim.x + threadIdx.x;
    if (d >= D_TOT) return;
    float a = ow[d];
#pragma unroll
    for (int j = 0; j < 40; j++)
        a = fmaf(s_np[j], P[(size_t)j * D_TOT + d], a);
    wt[d] = a;
}

// Permute weights into the exact smem image the conv consumes.
__global__ void wperm_k(const float* __restrict__ w, uint32_t* __restrict__ wp) {
    int i = blockIdx.x * blockDim.x + threadIdx.x;
    if (i >= WP_TOT) return;
    int l = 18;
    while (l > 0 && i < c_PO[l]) l--;
    const int r     = i - c_PO[l];
    const int CINR  = c_LCIN[l];
    const int ICC   = c_LICC[l];
    const int COUT  = c_LCOUT[l];
    const int PITCH = c_LPITCH[l];
    const int K     = ICC * 9;
    const int NG    = ICC / 8;
    const int cs    = COUT * PITCH;
    const int ch    = r / cs;
    const int r2    = r - ch * cs;
    const int oc    = r2 / PITCH;
    const int pos   = r2 - oc * PITCH;
    float v = 0.f;
    if (pos < K) {
        const int s    = pos >> 3, phys = pos & 7;
        const int u    = (phys & 1) ? (phys >> 1) + 4 : (phys >> 1);
        const int k    = s / NG, icg = s - (s / NG) * NG;
        const int ic   = ch * ICC + icg * 8 + u;
        if (ic < CINR) v = w[c_WOFF[l] + (oc * CINR + ic) * 9 + k];
    }
    wp[i] = f2tf32(v);
}

// ---------------------------------------------------------------------------
// Direct-from-tile tensor-core conv, channel-last activations.
//  CLIN: input (and prev/fused) are channel-last [n][y][x][c]; otherwise NCHW
//  (layer 0 only). Output is ALWAYS channel-last.
//  MT = m16-tiles per warp; positions per CTA = 128*MT. MINB = min blocks/SM.
//  MODE 0: plain; 1: relu(bn(in)); 2: +identity prev; 3: +padded/strided prev.
//  WF: also write transformed activation to `fused` (channel-last).
// ---------------------------------------------------------------------------
template<int CINR, int CINP, int COUT, int HIN, int STRIDE, int ICC, int IMGS,
         int MT, int MODE, int CPREV, bool WF, int MINB, bool CLIN>
__global__ void __launch_bounds__(256, MINB)
convt_k(const float* __restrict__ in, const uint32_t* __restrict__ wpb,
        float* __restrict__ out, const double* __restrict__ st_in,
        double* __restrict__ st_out, const float* __restrict__ prev,
        float* __restrict__ fused)
{
    constexpr int W     = HIN / STRIDE;
    constexpr int NPOS  = W * W;
    constexpr int PC    = 128 * MT;              // positions per CTA
    constexpr int R     = PC / (W * IMGS);
    constexpr int SPI   = (IMGS == 1) ? (NPOS / PC) : 1;
    constexpr int TH    = (R - 1) * STRIDE + 3;
    constexpr int TW    = HIN + 2;
    constexpr int NG    = ICC / 8;
    constexpr int NCH   = CINP / ICC;
    constexpr int K     = ICC * 9;
    constexpr int PITCH = pitchf(K);
    constexpr int STEPS = K / 8;
    constexpr int NC    = COUT / 8;
    constexpr int TILEW = IMGS * TH * TW * ICC;
    constexpr int PADF  = (MODE == 3) ? (CINR - CPREV) / 2 : 0;

    extern __shared__ float smf[];
    float*    s_sc = smf;
    float*    s_sh = smf + 64;
    uint32_t* s_a  = (uint32_t*)(smf + 128);
    uint32_t* s_b  = s_a + TILEW;

    const int tid = threadIdx.x, wid = tid >> 5, lane = tid & 31;
    const int g = lane >> 2, t = lane & 3;

    const int img0 = (IMGS == 1) ? (blockIdx.x / SPI) : blockIdx.x * IMGS;
    const int r0   = (IMGS == 1) ? (blockIdx.x % SPI) * R : 0;

    if (MODE >= 1 && tid < CINR) {
        const double cnt = 1024.0 * HIN * HIN;
        double mm = st_in[tid*2]   / cnt;
        double vv = st_in[tid*2+1] / cnt - mm * mm;
        float rs = rsqrtf((float)vv + 1e-5f);
        s_sc[tid] = rs;
        s_sh[tid] = (float)(-mm) * rs;
    }
    if (MODE >= 1) __syncthreads();

    // row-base word offsets into the tile (rows g, g+8, ... per m16 tile)
    int basew[2 * MT];
#pragma unroll
    for (int i = 0; i < 2 * MT; i++) {
        const int p   = wid * (16 * MT) + i * 8 + g;
        const int img = p / (R * W);
        const int rem = p - img * (R * W);
        const int y   = rem / W, x = rem - (rem / W) * W;
        basew[i] = (((img * TH + y * STRIDE) * NG) * TW + x * STRIDE) * 8 + 2 * t;
    }

    float acc[MT][NC][4];
#pragma unroll
    for (int mt = 0; mt < MT; mt++)
#pragma unroll
        for (int nc = 0; nc < NC; nc++)
#pragma unroll
            for (int i = 0; i < 4; i++) acc[mt][nc][i] = 0.f;

    for (int ch = 0; ch < NCH; ch++) {
        const int ic0 = ch * ICC;
        __syncthreads();

        // ---- stage input tile (transform fused in) ----
        for (int idx = tid; idx < IMGS * TH * TW; idx += 256) {
            const int img = idx / (TH * TW);
            const int rr  = idx - img * (TH * TW);
            const int ty  = rr / TW, tx = rr - (rr / TW) * TW;
            const int yi  = r0 * STRIDE - 1 + ty;
            const int xi  = tx - 1;
            const bool ok = (unsigned)yi < (unsigned)HIN && (unsigned)xi < (unsigned)HIN;
            const int  n  = img0 + img;
            uint32_t* dst = s_a + ((img * TH + ty) * NG) * (TW * 8) + tx * 8;

            if (CLIN) {
                // channel-last: vectorized loads
                const float* gcl = in + (((size_t)n * HIN + yi) * HIN + xi) * CINR + ic0;
                const float* pcl = nullptr;
                if (MODE == 2)
                    pcl = prev + (((size_t)n * HIN + yi) * HIN + xi) * CPREV + ic0;
                if (MODE == 3)
                    pcl = prev + (((size_t)n * (2*HIN) + 2*yi) * (2*HIN) + 2*xi) * CPREV
                               + (ic0 - PADF);
                float* fcl = nullptr;
                if (WF) fcl = fused + (((size_t)n * HIN + yi) * HIN + xi) * CINR + ic0;
#pragma unroll
                for (int icg = 0; icg < NG; icg++) {
                    float4 a4 = make_float4(0.f,0.f,0.f,0.f);
                    float4 b4 = make_float4(0.f,0.f,0.f,0.f);
                    if (ok) {
                        a4 = *(const float4*)(gcl + icg * 8);
                        b4 = *(const float4*)(gcl + icg * 8 + 4);
                        if (MODE >= 1) {
                            const float4 sa = *(const float4*)&s_sc[ic0 + icg*8];
                            const float4 sb = *(const float4*)&s_sc[ic0 + icg*8 + 4];
                            const float4 ha = *(const float4*)&s_sh[ic0 + icg*8];
                            const float4 hb = *(const float4*)&s_sh[ic0 + icg*8 + 4];
                            a4.x = fmaf(a4.x, sa.x, ha.x); a4.y = fmaf(a4.y, sa.y, ha.y);
                            a4.z = fmaf(a4.z, sa.z, ha.z); a4.w = fmaf(a4.w, sa.w, ha.w);
                            b4.x = fmaf(b4.x, sb.x, hb.x); b4.y = fmaf(b4.y, sb.y, hb.y);
                            b4.z = fmaf(b4.z, sb.z, hb.z); b4.w = fmaf(b4.w, sb.w, hb.w);
                        }
                        if (MODE == 2) {
                            const float4 pa = *(const float4*)(pcl + icg * 8);
                            const float4 pb = *(const float4*)(pcl + icg * 8 + 4);
                            a4.x += pa.x; a4.y += pa.y; a4.z += pa.z; a4.w += pa.w;
                            b4.x += pb.x; b4.y += pb.y; b4.z += pb.z; b4.w += pb.w;
                        }
                        if (MODE == 3) {
                            const int gic0 = ic0 + icg * 8 - PADF;
                            if (gic0 >= 0 && gic0 + 8 <= CPREV) {
                                const float4 pa = *(const float4*)(pcl + icg * 8);
                                const float4 pb = *(const float4*)(pcl + icg * 8 + 4);
                                a4.x += pa.x; a4.y += pa.y; a4.z += pa.z; a4.w += pa.w;
                                b4.x += pb.x; b4.y += pb.y; b4.z += pb.z; b4.w += pb.w;
                            }
                        }
                        if (MODE >= 1) {
                            a4.x = fmaxf(a4.x, 0.f); a4.y = fmaxf(a4.y, 0.f);
                            a4.z = fmaxf(a4.z, 0.f); a4.w = fmaxf(a4.w, 0.f);
                            b4.x = fmaxf(b4.x, 0.f); b4.y = fmaxf(b4.y, 0.f);
                            b4.z = fmaxf(b4.z, 0.f); b4.w = fmaxf(b4.w, 0.f);
                        }
                        if (WF) {
                            *(float4*)(fcl + icg * 8)     = a4;
                            *(float4*)(fcl + icg * 8 + 4) = b4;
                        }
                    }
                    // permute to fragment order: (a.x,b.x,a.y,b.y,a.z,b.z,a.w,b.w)
                    uint4* d4 = (uint4*)(dst + icg * (TW * 8));
                    d4[0] = make_uint4(f2tf32(a4.x), f2tf32(b4.x),
                                       f2tf32(a4.y), f2tf32(b4.y));
                    d4[1] = make_uint4(f2tf32(a4.z), f2tf32(b4.z),
                                       f2tf32(a4.w), f2tf32(b4.w));
                }
            } else {
                // NCHW scalar path (layer 0 only: MODE 0, no prev, no WF)
                const float* gb = in + ((size_t)n * CINR + ic0) * HIN * HIN
                                     + yi * HIN + xi;
#pragma unroll
                for (int icg = 0; icg < NG; icg++) {
                    uint32_t wb8[8];
#pragma unroll
                    for (int j = 0; j < 4; j++) {
                        const int ia = icg * 8 + j, ib = ia + 4;
                        float va = 0.f, vb = 0.f;
                        if (ok) {
                            if (ic0 + ia < CINR) va = __ldg(gb + ia * HIN * HIN);
                            if (ic0 + ib < CINR) vb = __ldg(gb + ib * HIN * HIN);
                        }
                        wb8[2*j]     = f2tf32(va);
                        wb8[2*j + 1] = f2tf32(vb);
                    }
                    uint4* d4 = (uint4*)(dst + icg * (TW * 8));
                    d4[0] = make_uint4(wb8[0], wb8[1], wb8[2], wb8[3]);
                    d4[1] = make_uint4(wb8[4], wb8[5], wb8[6], wb8[7]);
                }
            }
        }

        // ---- stage B: plain vector copy of pre-permuted tf32 weights ----
        {
            const uint4* wb = (const uint4*)(wpb + ch * (COUT * PITCH));
            uint4* sb4 = (uint4*)s_b;
#pragma unroll 4
            for (int idx = tid; idx < COUT * PITCH / 4; idx += 256)
                sb4[idx] = wb[idx];
        }
        __syncthreads();

        // ---- MMA over STEPS k-slices ----
#pragma unroll
        for (int s = 0; s < STEPS; s++) {
            const int k   = s / NG;
            const int icg = s - k * NG;
            const int ky  = k / 3, kx = k - (k / 3) * 3;
            const int off = ((ky * NG + icg) * TW + kx) * 8;
            uint2 Af[2 * MT];
#pragma unroll
            for (int i = 0; i < 2 * MT; i++)
                Af[i] = *(const uint2*)(s_a + basew[i] + off);
#pragma unroll
            for (int nc = 0; nc < NC; nc++) {
                uint2 B = *(const uint2*)(s_b + (nc * 8 + g) * PITCH + s * 8 + 2 * t);
#pragma unroll
                for (int mt = 0; mt < MT; mt++)
                    mma_tf32(acc[mt][nc], Af[2*mt].x, Af[2*mt+1].x,
                             Af[2*mt].y, Af[2*mt+1].y, B.x, B.y);
            }
        }
    }

    __syncthreads();   // mainloop smem regions free from here
    float* s_st  = smf + 128;          // [PC][COUT]
    float* s_red = s_st + COUT * PC;   // [8 warps][COUT][2]

    // ---- BN stats straight from accumulators ----
#pragma unroll
    for (int nc = 0; nc < NC; nc++) {
        float s0 = 0.f, s1 = 0.f, q0 = 0.f, q1 = 0.f;
#pragma unroll
        for (int mt = 0; mt < MT; mt++) {
            s0 += acc[mt][nc][0] + acc[mt][nc][2];
            s1 += acc[mt][nc][1] + acc[mt][nc][3];
            q0 += acc[mt][nc][0]*acc[mt][nc][0] + acc[mt][nc][2]*acc[mt][nc][2];
            q1 += acc[mt][nc][1]*acc[mt][nc][1] + acc[mt][nc][3]*acc[mt][nc][3];
        }
#pragma unroll
        for (int off = 4; off < 32; off <<= 1) {
            s0 += __shfl_xor_sync(0xffffffffu, s0, off);
            s1 += __shfl_xor_sync(0xffffffffu, s1, off);
            q0 += __shfl_xor_sync(0xffffffffu, q0, off);
            q1 += __shfl_xor_sync(0xffffffffu, q1, off);
        }
        if (lane < 4) {
            const int cb = nc * 8 + 2 * lane;
            s_red[(wid * COUT + cb)     * 2 + 0] = s0;
            s_red[(wid * COUT + cb)     * 2 + 1] = q0;
            s_red[(wid * COUT + cb + 1) * 2 + 0] = s1;
            s_red[(wid * COUT + cb + 1) * 2 + 1] = q1;
        }
    }

    // ---- frags -> smem staging [PC][COUT] (float2 per frag pair) ----
#pragma unroll
    for (int mt = 0; mt < MT; mt++)
#pragma unroll
        for (int nc = 0; nc < NC; nc++) {
            const int cb = nc * 8 + 2 * t;
            const int p0 = wid * (16 * MT) + mt * 16 + g;
            *(float2*)&s_st[p0 * COUT + cb]       = make_float2(acc[mt][nc][0], acc[mt][nc][1]);
            *(float2*)&s_st[(p0 + 8) * COUT + cb] = make_float2(acc[mt][nc][2], acc[mt][nc][3]);
        }
    __syncthreads();

    // coalesced channel-last store (float4)
    for (int idx = tid; idx < COUT * PC / 4; idx += 256) {
        const int c4  = idx % (COUT / 4);
        const int lp  = idx / (COUT / 4);
        const int img = lp / (R * W);
        const int rem = lp - img * (R * W);
        const int y   = r0 + rem / W;
        const int x   = rem - (rem / W) * W;
        const float4 v = *(const float4*)&s_st[lp * COUT + c4 * 4];
        *(float4*)&out[(((size_t)(img0 + img) * W + y) * W + x) * COUT + c4 * 4] = v;
    }

    if (tid < COUT) {
        float s = 0.f, q = 0.f;
#pragma unroll
        for (int w8 = 0; w8 < 8; w8++) {
            s += s_red[(w8 * COUT + tid) * 2 + 0];
            q += s_red[(w8 * COUT + tid) * 2 + 1];
        }
        atomicAdd(&st_out[tid * 2 + 0], (double)s);
        atomicAdd(&st_out[tid * 2 + 1], (double)q);
    }
}

// ---------------------------------------------------------------------------
// Fused final residual + global average pool (8x8) + FC 64->10 (channel-last)
// ---------------------------------------------------------------------------
__global__ void __launch_bounds__(64)
poolfc_k(const float* __restrict__ h2, const double* __restrict__ st,
         const float* __restrict__ prev, const float* __restrict__ Wfc,
         const float* __restrict__ bfc, float* __restrict__ out)
{
    __shared__ float pooled[64];
    const int n = blockIdx.x, t = threadIdx.x;
    const double cnt = 1024.0 * 64.0;
    double m = st[t*2] / cnt;
    double v = st[t*2+1] / cnt - m * m;
    const float sc = rsqrtf((float)v + 1e-5f);
    const float sh = (float)(-m) * sc;
    const float* hp = h2   + (size_t)n * 64 * 64;
    const float* pp = prev + (size_t)n * 64 * 64;
    float s = 0.f;
#pragma unroll
    for (int i = 0; i < 64; i++)
        s += fmaxf(fmaf(hp[i * 64 + t], sc, sh) + pp[i * 64 + t], 0.f);
    pooled[t] = s * (1.f / 64.f);
    __syncthreads();
    if (t < 10) {
        float a = bfc[t];
#pragma unroll
        for (int c = 0; c < 64; c++) a = fmaf(Wfc[t * 64 + c], pooled[c], a);
        out[n * 10 + t] = a;
    }
}

// ---------------------------------------------------------------------------
// Host-side smem size (mirror of kernel constants)
// ---------------------------------------------------------------------------
static constexpr int cm2(int CINP, int COUT, int HIN, int STRIDE, int ICC,
                         int IMGS, int MT) {
    int W  = HIN / STRIDE;
    int PC = 128 * MT;
    int R  = PC / (W * IMGS);
    int TH = (R - 1) * STRIDE + 3;
    int TW = HIN + 2;
    int K  = ICC * 9;
    int P  = pitchf(K);
    int tile = IMGS * TH * TW * ICC;
    int p1 = tile + COUT * P;
    int p2 = COUT * PC + 16 * COUT;
    int m  = (p1 > p2) ? p1 : p2;
    return (128 + m) * 4;
}

extern "C" void kernel_launch(void* const* d_in, const int* in_sizes, int n_in,
                              void* d_out, int out_size)
{
    (void)in_sizes; (void)n_in; (void)out_size;
    const float* x   = (const float*)d_in[0];
    const float* ow  = (const float*)d_in[1];
    const float* P   = (const float*)d_in[2];
    const float* npar= (const float*)d_in[3];
    const float* Wfc = (const float*)d_in[4];
    const float* bfc = (const float*)d_in[5];
    float* y = (float*)d_out;

    float *A, *B, *C, *D, *w; uint32_t* wp; double* st;
    cudaGetSymbolAddress((void**)&A,  g_bufA);
    cudaGetSymbolAddress((void**)&B,  g_bufB);
    cudaGetSymbolAddress((void**)&C,  g_bufC);
    cudaGetSymbolAddress((void**)&D,  g_bufD);
    cudaGetSymbolAddress((void**)&w,  g_w);
    cudaGetSymbolAddress((void**)&wp, g_wp);
    cudaGetSymbolAddress((void**)&st, g_stats);

    #define SETSM(FN, CINP_, COUT_, HIN_, STRIDE_, ICC_, IMGS_, MT_) \
        cudaFuncSetAttribute(FN, cudaFuncAttributeMaxDynamicSharedMemorySize, \
                             cm2(CINP_, COUT_, HIN_, STRIDE_, ICC_, IMGS_, MT_))

    auto I0  = convt_k< 3, 8,16,32,1, 8,1,2,0, 0,false,5,false>; SETSM(I0,  8,16,32,1, 8,1,2);
    auto I1  = convt_k<16,16,16,32,1,16,1,2,1, 0,true ,5,true >; SETSM(I1, 16,16,32,1,16,1,2);
    auto I2  = convt_k<16,16,16,32,1,16,1,2,1, 0,false,5,true >; SETSM(I2, 16,16,32,1,16,1,2);
    auto I3  = convt_k<16,16,16,32,1,16,1,2,2,16,true ,5,true >; SETSM(I3, 16,16,32,1,16,1,2);
    auto I4  = convt_k<16,16,32,32,2, 8,1,2,2,16,true ,4,true >; SETSM(I4, 16,32,32,2, 8,1,2);
    auto I5  = convt_k<32,32,32,16,1, 8,1,2,1, 0,false,4,true >; SETSM(I5, 32,32,16,1, 8,1,2);
    auto I6  = convt_k<32,32,32,16,1, 8,1,2,3,16,true ,4,true >; SETSM(I6, 32,32,16,1, 8,1,2);
    auto I7  = convt_k<32,32,32,16,1, 8,1,2,2,32,true ,4,true >; SETSM(I7, 32,32,16,1, 8,1,2);
    auto I8  = convt_k<32,32,64,16,2, 8,4,2,2,32,true ,2,true >; SETSM(I8, 32,64,16,2, 8,4,2);
    auto I9  = convt_k<64,64,64, 8,1,16,4,2,1, 0,false,2,true >; SETSM(I9, 64,64, 8,1,16,4,2);
    auto I10 = convt_k<64,64,64, 8,1,16,4,2,3,32,true ,2,true >; SETSM(I10,64,64, 8,1,16,4,2);
    auto I11 = convt_k<64,64,64, 8,1,16,4,2,2,64,true ,2,true >; SETSM(I11,64,64, 8,1,16,4,2);
    #undef SETSM

    auto ST = [&](int l) { return st + l * 128; };
    auto WL = [&](int l) { return wp + PO_H[l]; };

    zstats_k<<<(19*64*2 + 255)/256, 256>>>(st);
    wbuild_k<<<(D_TOT + 255)/256, 256>>>(ow, P, npar, w);
    wperm_k<<<(WP_TOT + 255)/256, 256>>>(w, wp);

    const int S1 = cm2( 8,16,32,1, 8,1,2);
    const int S2 = cm2(16,16,32,1,16,1,2);
    const int S3 = cm2(16,32,32,2, 8,1,2);
    const int S4 = cm2(32,32,16,1, 8,1,2);
    const int S5 = cm2(32,64,16,2, 8,4,2);
    const int S6 = cm2(64,64, 8,1,16,4,2);

    // layer 0 (NCHW input -> channel-last output)
    I0 <<<4096,256,S1>>>(x, WL(0), A, nullptr, ST(0), nullptr, nullptr);
    // block 1
    I1 <<<4096,256,S2>>>(A, WL(1), B, ST(0),  ST(1), nullptr, C);
    I2 <<<4096,256,S2>>>(B, WL(2), A, ST(1),  ST(2), nullptr, nullptr);
    // block 2
    I3 <<<4096,256,S2>>>(A, WL(3), B, ST(2),  ST(3), C, D);
    I2 <<<4096,256,S2>>>(B, WL(4), C, ST(3),  ST(4), nullptr, nullptr);
    // block 3
    I3 <<<4096,256,S2>>>(C, WL(5), B, ST(4),  ST(5), D, A);
    I2 <<<4096,256,S2>>>(B, WL(6), D, ST(5),  ST(6), nullptr, nullptr);
    // block 4 (16->32, stride 2)
    I4 <<<1024,256,S3>>>(D, WL(7), B, ST(6),  ST(7), A, C);
    I5 <<<1024,256,S4>>>(B, WL(8), A, ST(7),  ST(8), nullptr, nullptr);
    // block 5 (MODE3 pad shortcut, prev 16ch@32)
    I6 <<<1024,256,S4>>>(A, WL(9), B, ST(8),  ST(9), C, D);
    I5 <<<1024,256,S4>>>(B, WL(10),C, ST(9),  ST(10),nullptr, nullptr);
    // block 6
    I7 <<<1024,256,S4>>>(C, WL(11),B, ST(10), ST(11),D, A);
    I5 <<<1024,256,S4>>>(B, WL(12),D, ST(11), ST(12),nullptr, nullptr);
    // block 7 (32->64, stride 2)
    I8 <<< 256,256,S5>>>(D, WL(13),B, ST(12), ST(13),A, C);
    I9 <<< 256,256,S6>>>(B, WL(14),A, ST(13), ST(14),nullptr, nullptr);
    // block 8 (MODE3 pad shortcut, prev 32ch@16)
    I10<<< 256,256,S6>>>(A, WL(15),B, ST(14), ST(15),C, D);
    I9 <<< 256,256,S6>>>(B, WL(16),C, ST(15), ST(16),nullptr, nullptr);
    // block 9
    I11<<< 256,256,S6>>>(C, WL(17),B, ST(16), ST(17),D, A);
    I9 <<< 256,256,S6>>>(B, WL(18),D, ST(17), ST(18),nullptr, nullptr);
    // fused final residual + pool + fc
    poolfc_k<<<NB,64>>>(D, ST(18), A, Wfc, bfc, y);
}

// round 12
// speedup vs baseline: 1.1303x; 1.0049x over previous
#include <cuda_runtime.h>
#include <cuda_bf16.h>
#include <cstdint>
#include <cstdio>

// ---------------------------------------------------------------------------
// Problem constants
// ---------------------------------------------------------------------------
#define NB 1024
static const int D_TOT = 267696;

// permuted tf32 weight buffer offsets (see wperm_k); ICC per layer:
// {8,16,16,16,16,16,16,8,8,8,8,8,8,8,16,16,16,16,16}
static const int PO_H[19] = {0,1152,3584,6016,8448,10880,13312,15744,20352,29568,
                             38784,48000,57216,66432,84864,123776,162688,201600,240512};
#define WP_TOT 279424

__constant__ int c_PO[19]   = {0,1152,3584,6016,8448,10880,13312,15744,20352,29568,
                               38784,48000,57216,66432,84864,123776,162688,201600,240512};
__constant__ int c_WOFF[19] = {0,432,2736,5040,7344,9648,11952,14256,18864,28080,
                               37296,46512,55728,64944,83376,120240,157104,193968,230832};
__constant__ int c_LCIN[19]  = {3,16,16,16,16,16,16,16,32,32,32,32,32,32,64,64,64,64,64};
__constant__ int c_LICC[19]  = {8,16,16,16,16,16,16,8,8,8,8,8,8,8,16,16,16,16,16};
__constant__ int c_LCOUT[19] = {16,16,16,16,16,16,16,32,32,32,32,32,32,64,64,64,64,64,64};
__constant__ int c_LPITCH[19]= {72,152,152,152,152,152,152,72,72,72,72,72,72,72,152,152,152,152,152};

// ---------------------------------------------------------------------------
// Device scratch
// ---------------------------------------------------------------------------
#define BUF_ELEMS (1024*16*32*32)
__device__ float    g_bufA[BUF_ELEMS];
__device__ float    g_bufB[BUF_ELEMS];
__device__ float    g_bufC[BUF_ELEMS];
__device__ float    g_bufD[BUF_ELEMS];
__device__ float    g_w[267696];       // natural per-layer layout: [oc][ic][3][3]
__device__ uint32_t g_wp[WP_TOT];      // permuted tf32 smem-image weights
__device__ double   g_stats[19*64*2];  // per layer, per channel: sum, sumsq

// ---------------------------------------------------------------------------
// helpers
// ---------------------------------------------------------------------------
__host__ __device__ constexpr int pitchf(int K) {
    int p = K;
    while (!((p % 32) == 8 || (p % 32) == 24)) p++;
    return p;
}
__device__ __forceinline__ uint32_t f2tf32(float v) {
    uint32_t u; asm("cvt.rna.tf32.f32 %0, %1;" : "=r"(u) : "f"(v)); return u;
}
__device__ __forceinline__ void mma_tf32(float c[4],
                                         uint32_t a0, uint32_t a1, uint32_t a2, uint32_t a3,
                                         uint32_t b0, uint32_t b1) {
    asm volatile(
        "mma.sync.aligned.m16n8k8.row.col.f32.tf32.tf32.f32 "
        "{%0,%1,%2,%3}, {%4,%5,%6,%7}, {%8,%9}, {%0,%1,%2,%3};"
        : "+f"(c[0]), "+f"(c[1]), "+f"(c[2]), "+f"(c[3])
        : "r"(a0), "r"(a1), "r"(a2), "r"(a3), "r"(b0), "r"(b1));
}

// ---------------------------------------------------------------------------
__global__ void zstats_k(double* __restrict__ st) {
    int i = blockIdx.x * blockDim.x + threadIdx.x;
    if (i < 19*64*2) st[i] = 0.0;
}

__global__ void wbuild_k(const float* __restrict__ ow, const float* __restrict__ P,
                         const float* __restrict__ npar, float* __restrict__ wt) {
    __shared__ float s_np[40];
    if (threadIdx.x < 40) s_np[threadIdx.x] = npar[threadIdx.x];
    __syncthreads();
    int d = blockIdx.x * blockDim.x + threadIdx.x;
    if (d >= D_TOT) return;
    float a = ow[d];
#pragma unroll
    for (int j = 0; j < 40; j++)
        a = fmaf(s_np[j], P[(size_t)j * D_TOT + d], a);
    wt[d] = a;
}

// Permute weights into the exact smem image the conv consumes.
__global__ void wperm_k(const float* __restrict__ w, uint32_t* __restrict__ wp) {
    int i = blockIdx.x * blockDim.x + threadIdx.x;
    if (i >= WP_TOT) return;
    int l = 18;
    while (l > 0 && i < c_PO[l]) l--;
    const int r     = i - c_PO[l];
    const int CINR  = c_LCIN[l];
    const int ICC   = c_LICC[l];
    const int COUT  = c_LCOUT[l];
    const int PITCH = c_LPITCH[l];
    const int K     = ICC * 9;
    const int NG    = ICC / 8;
    const int cs    = COUT * PITCH;
    const int ch    = r / cs;
    const int r2    = r - ch * cs;
    const int oc    = r2 / PITCH;
    const int pos   = r2 - oc * PITCH;
    float v = 0.f;
    if (pos < K) {
        const int s    = pos >> 3, phys = pos & 7;
        const int u    = (phys & 1) ? (phys >> 1) + 4 : (phys >> 1);
        const int k    = s / NG, icg = s - (s / NG) * NG;
        const int ic   = ch * ICC + icg * 8 + u;
        if (ic < CINR) v = w[c_WOFF[l] + (oc * CINR + ic) * 9 + k];
    }
    wp[i] = f2tf32(v);
}

// Transpose NCHW 3-channel input to NHWC-8 (channels 3..7 zero).
__global__ void __launch_bounds__(256)
xpose_k(const float* __restrict__ in, float* __restrict__ out) {
    const int idx = blockIdx.x * 256 + threadIdx.x;   // (n*1024 + y*32 + x)
    const int n  = idx >> 10;
    const int hw = idx & 1023;
    const float* ib = in + (size_t)n * 3 * 1024 + hw;
    float4 a = make_float4(__ldg(ib), __ldg(ib + 1024), __ldg(ib + 2048), 0.f);
    float4 b = make_float4(0.f, 0.f, 0.f, 0.f);
    float4* ob = (float4*)(out + (size_t)idx * 8);
    ob[0] = a;
    ob[1] = b;
}

// ---------------------------------------------------------------------------
// Direct-from-tile tensor-core conv, channel-last activations.
//  Staging is two-phase per iteration: batch-issue ALL loads (input + shortcut)
//  first, then transform + store -> high MLP, one memory round instead of two.
//  MT = m16-tiles per warp; positions per CTA = 128*MT. MINB = min blocks/SM.
//  MODE 0: plain; 1: relu(bn(in)); 2: +identity prev; 3: +padded/strided prev.
//  WF: also write transformed activation to `fused` (channel-last).
// ---------------------------------------------------------------------------
template<int CINR, int CINP, int COUT, int HIN, int STRIDE, int ICC, int IMGS,
         int MT, int MODE, int CPREV, bool WF, int MINB>
__global__ void __launch_bounds__(256, MINB)
convt_k(const float* __restrict__ in, const uint32_t* __restrict__ wpb,
        float* __restrict__ out, const double* __restrict__ st_in,
        double* __restrict__ st_out, const float* __restrict__ prev,
        float* __restrict__ fused)
{
    constexpr int W     = HIN / STRIDE;
    constexpr int NPOS  = W * W;
    constexpr int PC    = 128 * MT;              // positions per CTA
    constexpr int R     = PC / (W * IMGS);
    constexpr int SPI   = (IMGS == 1) ? (NPOS / PC) : 1;
    constexpr int TH    = (R - 1) * STRIDE + 3;
    constexpr int TW    = HIN + 2;
    constexpr int NG    = ICC / 8;
    constexpr int NCH   = CINP / ICC;
    constexpr int K     = ICC * 9;
    constexpr int PITCH = pitchf(K);
    constexpr int STEPS = K / 8;
    constexpr int NC    = COUT / 8;
    constexpr int TILEW = IMGS * TH * TW * ICC;
    constexpr int PADF  = (MODE == 3) ? (CINR - CPREV) / 2 : 0;

    extern __shared__ float smf[];
    float*    s_sc = smf;
    float*    s_sh = smf + 64;
    uint32_t* s_a  = (uint32_t*)(smf + 128);
    uint32_t* s_b  = s_a + TILEW;

    const int tid = threadIdx.x, wid = tid >> 5, lane = tid & 31;
    const int g = lane >> 2, t = lane & 3;

    const int img0 = (IMGS == 1) ? (blockIdx.x / SPI) : blockIdx.x * IMGS;
    const int r0   = (IMGS == 1) ? (blockIdx.x % SPI) * R : 0;

    if (MODE >= 1 && tid < CINR) {
        const double cnt = 1024.0 * HIN * HIN;
        double mm = st_in[tid*2]   / cnt;
        double vv = st_in[tid*2+1] / cnt - mm * mm;
        float rs = rsqrtf((float)vv + 1e-5f);
        s_sc[tid] = rs;
        s_sh[tid] = (float)(-mm) * rs;
    }
    if (MODE >= 1) __syncthreads();

    // row-base word offsets into the tile (rows g, g+8, ... per m16 tile)
    int basew[2 * MT];
#pragma unroll
    for (int i = 0; i < 2 * MT; i++) {
        const int p   = wid * (16 * MT) + i * 8 + g;
        const int img = p / (R * W);
        const int rem = p - img * (R * W);
        const int y   = rem / W, x = rem - (rem / W) * W;
        basew[i] = (((img * TH + y * STRIDE) * NG) * TW + x * STRIDE) * 8 + 2 * t;
    }

    float acc[MT][NC][4];
#pragma unroll
    for (int mt = 0; mt < MT; mt++)
#pragma unroll
        for (int nc = 0; nc < NC; nc++)
#pragma unroll
            for (int i = 0; i < 4; i++) acc[mt][nc][i] = 0.f;

    for (int ch = 0; ch < NCH; ch++) {
        const int ic0 = ch * ICC;
        __syncthreads();

        // ---- stage input tile: phase-1 batch loads, phase-2 transform+store ----
        for (int idx = tid; idx < IMGS * TH * TW; idx += 256) {
            const int img = idx / (TH * TW);
            const int rr  = idx - img * (TH * TW);
            const int ty  = rr / TW, tx = rr - (rr / TW) * TW;
            const int yi  = r0 * STRIDE - 1 + ty;
            const int xi  = tx - 1;
            const bool ok = (unsigned)yi < (unsigned)HIN && (unsigned)xi < (unsigned)HIN;
            const int  n  = img0 + img;
            uint32_t* dst = s_a + ((img * TH + ty) * NG) * (TW * 8) + tx * 8;

            const float* gcl = in + (((size_t)n * HIN + yi) * HIN + xi) * CINR + ic0;
            const float* pcl = nullptr;
            if (MODE == 2)
                pcl = prev + (((size_t)n * HIN + yi) * HIN + xi) * CPREV + ic0;
            if (MODE == 3)
                pcl = prev + (((size_t)n * (2*HIN) + 2*yi) * (2*HIN) + 2*xi) * CPREV
                           + (ic0 - PADF);
            float* fcl = nullptr;
            if (WF) fcl = fused + (((size_t)n * HIN + yi) * HIN + xi) * CINR + ic0;

            // phase 1: issue all loads (input + shortcut) concurrently
            float4 ia[NG][2], pa[NG][2];
#pragma unroll
            for (int icg = 0; icg < NG; icg++) {
                if (ok) {
                    ia[icg][0] = *(const float4*)(gcl + icg * 8);
                    ia[icg][1] = *(const float4*)(gcl + icg * 8 + 4);
                } else {
                    ia[icg][0] = make_float4(0.f,0.f,0.f,0.f);
                    ia[icg][1] = make_float4(0.f,0.f,0.f,0.f);
                }
            }
            if (MODE == 2 || MODE == 3) {
#pragma unroll
                for (int icg = 0; icg < NG; icg++) {
                    bool pv = ok;
                    if (MODE == 3) {
                        const int gic0 = ic0 + icg * 8 - PADF;
                        pv = ok && (gic0 >= 0) && (gic0 + 8 <= CPREV);
                    }
                    if (pv) {
                        pa[icg][0] = *(const float4*)(pcl + icg * 8);
                        pa[icg][1] = *(const float4*)(pcl + icg * 8 + 4);
                    } else {
                        pa[icg][0] = make_float4(0.f,0.f,0.f,0.f);
                        pa[icg][1] = make_float4(0.f,0.f,0.f,0.f);
                    }
                }
            }

            // phase 2: transform + store
#pragma unroll
            for (int icg = 0; icg < NG; icg++) {
                float4 a4 = ia[icg][0], b4 = ia[icg][1];
                if (MODE >= 1 && ok) {
                    const float4 sa = *(const float4*)&s_sc[ic0 + icg*8];
                    const float4 sb = *(const float4*)&s_sc[ic0 + icg*8 + 4];
                    const float4 ha = *(const float4*)&s_sh[ic0 + icg*8];
                    const float4 hb = *(const float4*)&s_sh[ic0 + icg*8 + 4];
                    a4.x = fmaf(a4.x, sa.x, ha.x); a4.y = fmaf(a4.y, sa.y, ha.y);
                    a4.z = fmaf(a4.z, sa.z, ha.z); a4.w = fmaf(a4.w, sa.w, ha.w);
                    b4.x = fmaf(b4.x, sb.x, hb.x); b4.y = fmaf(b4.y, sb.y, hb.y);
                    b4.z = fmaf(b4.z, sb.z, hb.z); b4.w = fmaf(b4.w, sb.w, hb.w);
                    if (MODE >= 2) {
                        a4.x += pa[icg][0].x; a4.y += pa[icg][0].y;
                        a4.z += pa[icg][0].z; a4.w += pa[icg][0].w;
                        b4.x += pa[icg][1].x; b4.y += pa[icg][1].y;
                        b4.z += pa[icg][1].z; b4.w += pa[icg][1].w;
                    }
                    a4.x = fmaxf(a4.x, 0.f); a4.y = fmaxf(a4.y, 0.f);
                    a4.z = fmaxf(a4.z, 0.f); a4.w = fmaxf(a4.w, 0.f);
                    b4.x = fmaxf(b4.x, 0.f); b4.y = fmaxf(b4.y, 0.f);
                    b4.w = fmaxf(b4.w, 0.f); b4.z = fmaxf(b4.z, 0.f);
                }
                if (WF && ok) {
                    *(float4*)(fcl + icg * 8)     = a4;
                    *(float4*)(fcl + icg * 8 + 4) = b4;
                }
                // permute to fragment order: (a.x,b.x,a.y,b.y,a.z,b.z,a.w,b.w)
                uint4* d4 = (uint4*)(dst + icg * (TW * 8));
                d4[0] = make_uint4(f2tf32(a4.x), f2tf32(b4.x),
                                   f2tf32(a4.y), f2tf32(b4.y));
                d4[1] = make_uint4(f2tf32(a4.z), f2tf32(b4.z),
                                   f2tf32(a4.w), f2tf32(b4.w));
            }
        }

        // ---- stage B: plain vector copy of pre-permuted tf32 weights ----
        {
            const uint4* wb = (const uint4*)(wpb + ch * (COUT * PITCH));
            uint4* sb4 = (uint4*)s_b;
#pragma unroll 4
            for (int idx = tid; idx < COUT * PITCH / 4; idx += 256)
                sb4[idx] = wb[idx];
        }
        __syncthreads();

        // ---- MMA over STEPS k-slices ----
#pragma unroll
        for (int s = 0; s < STEPS; s++) {
            const int k   = s / NG;
            const int icg = s - k * NG;
            const int ky  = k / 3, kx = k - (k / 3) * 3;
            const int off = ((ky * NG + icg) * TW + kx) * 8;
            uint2 Af[2 * MT];
#pragma unroll
            for (int i = 0; i < 2 * MT; i++)
                Af[i] = *(const uint2*)(s_a + basew[i] + off);
#pragma unroll
            for (int nc = 0; nc < NC; nc++) {
                uint2 B = *(const uint2*)(s_b + (nc * 8 + g) * PITCH + s * 8 + 2 * t);
#pragma unroll
                for (int mt = 0; mt < MT; mt++)
                    mma_tf32(acc[mt][nc], Af[2*mt].x, Af[2*mt+1].x,
                             Af[2*mt].y, Af[2*mt+1].y, B.x, B.y);
            }
        }
    }

    __syncthreads();   // mainloop smem regions free from here
    float* s_st  = smf + 128;          // [PC][COUT]
    float* s_red = s_st + COUT * PC;   // [8 warps][COUT][2]

    // ---- BN stats straight from accumulators ----
#pragma unroll
    for (int nc = 0; nc < NC; nc++) {
        float s0 = 0.f, s1 = 0.f, q0 = 0.f, q1 = 0.f;
#pragma unroll
        for (int mt = 0; mt < MT; mt++) {
            s0 += acc[mt][nc][0] + acc[mt][nc][2];
            s1 += acc[mt][nc][1] + acc[mt][nc][3];
            q0 += acc[mt][nc][0]*acc[mt][nc][0] + acc[mt][nc][2]*acc[mt][nc][2];
            q1 += acc[mt][nc][1]*acc[mt][nc][1] + acc[mt][nc][3]*acc[mt][nc][3];
        }
#pragma unroll
        for (int off = 4; off < 32; off <<= 1) {
            s0 += __shfl_xor_sync(0xffffffffu, s0, off);
            s1 += __shfl_xor_sync(0xffffffffu, s1, off);
            q0 += __shfl_xor_sync(0xffffffffu, q0, off);
            q1 += __shfl_xor_sync(0xffffffffu, q1, off);
        }
        if (lane < 4) {
            const int cb = nc * 8 + 2 * lane;
            s_red[(wid * COUT + cb)     * 2 + 0] = s0;
            s_red[(wid * COUT + cb)     * 2 + 1] = q0;
            s_red[(wid * COUT + cb + 1) * 2 + 0] = s1;
            s_red[(wid * COUT + cb + 1) * 2 + 1] = q1;
        }
    }

    // ---- frags -> smem staging [PC][COUT] (float2 per frag pair) ----
#pragma unroll
    for (int mt = 0; mt < MT; mt++)
#pragma unroll
        for (int nc = 0; nc < NC; nc++) {
            const int cb = nc * 8 + 2 * t;
            const int p0 = wid * (16 * MT) + mt * 16 + g;
            *(float2*)&s_st[p0 * COUT + cb]       = make_float2(acc[mt][nc][0], acc[mt][nc][1]);
            *(float2*)&s_st[(p0 + 8) * COUT + cb] = make_float2(acc[mt][nc][2], acc[mt][nc][3]);
        }
    __syncthreads();

    // coalesced channel-last store (float4)
    for (int idx = tid; idx < COUT * PC / 4; idx += 256) {
        const int c4  = idx % (COUT / 4);
        const int lp  = idx / (COUT / 4);
        const int img = lp / (R * W);
        const int rem = lp - img * (R * W);
        const int y   = r0 + rem / W;
        const int x   = rem - (rem / W) * W;
        const float4 v = *(const float4*)&s_st[lp * COUT + c4 * 4];
        *(float4*)&out[(((size_t)(img0 + img) * W + y) * W + x) * COUT + c4 * 4] = v;
    }

    if (tid < COUT) {
        float s = 0.f, q = 0.f;
#pragma unroll
        for (int w8 = 0; w8 < 8; w8++) {
            s += s_red[(w8 * COUT + tid) * 2 + 0];
            q += s_red[(w8 * COUT + tid) * 2 + 1];
        }
        atomicAdd(&st_out[tid * 2 + 0], (double)s);
        atomicAdd(&st_out[tid * 2 + 1], (double)q);
    }
}

// ---------------------------------------------------------------------------
// Fused final residual + global average pool (8x8) + FC 64->10 (channel-last)
// ---------------------------------------------------------------------------
__global__ void __launch_bounds__(64)
poolfc_k(const float* __restrict__ h2, const double* __restrict__ st,
         const float* __restrict__ prev, const float* __restrict__ Wfc,
         const float* __restrict__ bfc, float* __restrict__ out)
{
    __shared__ float pooled[64];
    const int n = blockIdx.x, t = threadIdx.x;
    const double cnt = 1024.0 * 64.0;
    double m = st[t*2] / cnt;
    double v = st[t*2+1] / cnt - m * m;
    const float sc = rsqrtf((float)v + 1e-5f);
    const float sh = (float)(-m) * sc;
    const float* hp = h2   + (size_t)n * 64 * 64;
    const float* pp = prev + (size_t)n * 64 * 64;
    float s = 0.f;
#pragma unroll
    for (int i = 0; i < 64; i++)
        s += fmaxf(fmaf(hp[i * 64 + t], sc, sh) + pp[i * 64 + t], 0.f);
    pooled[t] = s * (1.f / 64.f);
    __syncthreads();
    if (t < 10) {
        float a = bfc[t];
#pragma unroll
        for (int c = 0; c < 64; c++) a = fmaf(Wfc[t * 64 + c], pooled[c], a);
        out[n * 10 + t] = a;
    }
}

// ---------------------------------------------------------------------------
// Host-side smem size (mirror of kernel constants)
// ---------------------------------------------------------------------------
static constexpr int cm2(int CINP, int COUT, int HIN, int STRIDE, int ICC,
                         int IMGS, int MT) {
    int W  = HIN / STRIDE;
    int PC = 128 * MT;
    int R  = PC / (W * IMGS);
    int TH = (R - 1) * STRIDE + 3;
    int TW = HIN + 2;
    int K  = ICC * 9;
    int P  = pitchf(K);
    int tile = IMGS * TH * TW * ICC;
    int p1 = tile + COUT * P;
    int p2 = COUT * PC + 16 * COUT;
    int m  = (p1 > p2) ? p1 : p2;
    return (128 + m) * 4;
}

extern "C" void kernel_launch(void* const* d_in, const int* in_sizes, int n_in,
                              void* d_out, int out_size)
{
    (void)in_sizes; (void)n_in; (void)out_size;
    const float* x   = (const float*)d_in[0];
    const float* ow  = (const float*)d_in[1];
    const float* P   = (const float*)d_in[2];
    const float* npar= (const float*)d_in[3];
    const float* Wfc = (const float*)d_in[4];
    const float* bfc = (const float*)d_in[5];
    float* y = (float*)d_out;

    float *A, *B, *C, *D, *w; uint32_t* wp; double* st;
    cudaGetSymbolAddress((void**)&A,  g_bufA);
    cudaGetSymbolAddress((void**)&B,  g_bufB);
    cudaGetSymbolAddress((void**)&C,  g_bufC);
    cudaGetSymbolAddress((void**)&D,  g_bufD);
    cudaGetSymbolAddress((void**)&w,  g_w);
    cudaGetSymbolAddress((void**)&wp, g_wp);
    cudaGetSymbolAddress((void**)&st, g_stats);

    #define SETSM(FN, CINP_, COUT_, HIN_, STRIDE_, ICC_, IMGS_, MT_) \
        cudaFuncSetAttribute(FN, cudaFuncAttributeMaxDynamicSharedMemorySize, \
                             cm2(CINP_, COUT_, HIN_, STRIDE_, ICC_, IMGS_, MT_))

    auto I0  = convt_k< 8, 8,16,32,1, 8,1,2,0, 0,false,5>; SETSM(I0,  8,16,32,1, 8,1,2);
    auto I1  = convt_k<16,16,16,32,1,16,1,2,1, 0,true ,5>; SETSM(I1, 16,16,32,1,16,1,2);
    auto I2  = convt_k<16,16,16,32,1,16,1,2,1, 0,false,5>; SETSM(I2, 16,16,32,1,16,1,2);
    auto I3  = convt_k<16,16,16,32,1,16,1,2,2,16,true ,4>; SETSM(I3, 16,16,32,1,16,1,2);
    auto I4  = convt_k<16,16,32,32,2, 8,1,2,2,16,true ,4>; SETSM(I4, 16,32,32,2, 8,1,2);
    auto I5  = convt_k<32,32,32,16,1, 8,1,2,1, 0,false,4>; SETSM(I5, 32,32,16,1, 8,1,2);
    auto I6  = convt_k<32,32,32,16,1, 8,1,2,3,16,true ,4>; SETSM(I6, 32,32,16,1, 8,1,2);
    auto I7  = convt_k<32,32,32,16,1, 8,1,2,2,32,true ,4>; SETSM(I7, 32,32,16,1, 8,1,2);
    auto I8  = convt_k<32,32,64,16,2, 8,4,2,2,32,true ,2>; SETSM(I8, 32,64,16,2, 8,4,2);
    auto I9  = convt_k<64,64,64, 8,1,16,4,2,1, 0,false,2>; SETSM(I9, 64,64, 8,1,16,4,2);
    auto I10 = convt_k<64,64,64, 8,1,16,4,2,3,32,true ,2>; SETSM(I10,64,64, 8,1,16,4,2);
    auto I11 = convt_k<64,64,64, 8,1,16,4,2,2,64,true ,2>; SETSM(I11,64,64, 8,1,16,4,2);
    #undef SETSM

    auto ST = [&](int l) { return st + l * 128; };
    auto WL = [&](int l) { return wp + PO_H[l]; };

    zstats_k<<<(19*64*2 + 255)/256, 256>>>(st);
    wbuild_k<<<(D_TOT + 255)/256, 256>>>(ow, P, npar, w);
    wperm_k<<<(WP_TOT + 255)/256, 256>>>(w, wp);
    xpose_k<<<4096, 256>>>(x, D);   // NCHW 3ch -> NHWC-8 (zero padded)

    const int S1 = cm2( 8,16,32,1, 8,1,2);
    const int S2 = cm2(16,16,32,1,16,1,2);
    const int S3 = cm2(16,32,32,2, 8,1,2);
    const int S4 = cm2(32,32,16,1, 8,1,2);
    const int S5 = cm2(32,64,16,2, 8,4,2);
    const int S6 = cm2(64,64, 8,1,16,4,2);

    // layer 0 (channel-last padded input in D)
    I0 <<<4096,256,S1>>>(D, WL(0), A, nullptr, ST(0), nullptr, nullptr);
    // block 1
    I1 <<<4096,256,S2>>>(A, WL(1), B, ST(0),  ST(1), nullptr, C);
    I2 <<<4096,256,S2>>>(B, WL(2), A, ST(1),  ST(2), nullptr, nullptr);
    // block 2
    I3 <<<4096,256,S2>>>(A, WL(3), B, ST(2),  ST(3), C, D);
    I2 <<<4096,256,S2>>>(B, WL(4), C, ST(3),  ST(4), nullptr, nullptr);
    // block 3
    I3 <<<4096,256,S2>>>(C, WL(5), B, ST(4),  ST(5), D, A);
    I2 <<<4096,256,S2>>>(B, WL(6), D, ST(5),  ST(6), nullptr, nullptr);
    // block 4 (16->32, stride 2)
    I4 <<<1024,256,S3>>>(D, WL(7), B, ST(6),  ST(7), A, C);
    I5 <<<1024,256,S4>>>(B, WL(8), A, ST(7),  ST(8), nullptr, nullptr);
    // block 5 (MODE3 pad shortcut, prev 16ch@32)
    I6 <<<1024,256,S4>>>(A, WL(9), B, ST(8),  ST(9), C, D);
    I5 <<<1024,256,S4>>>(B, WL(10),C, ST(9),  ST(10),nullptr, nullptr);
    // block 6
    I7 <<<1024,256,S4>>>(C, WL(11),B, ST(10), ST(11),D, A);
    I5 <<<1024,256,S4>>>(B, WL(12),D, ST(11), ST(12),nullptr, nullptr);
    // block 7 (32->64, stride 2)
    I8 <<< 256,256,S5>>>(D, WL(13),B, ST(12), ST(13),A, C);
    I9 <<< 256,256,S6>>>(B, WL(14),A, ST(13), ST(14),nullptr, nullptr);
    // block 8 (MODE3 pad shortcut, prev 32ch@16)
    I10<<< 256,256,S6>>>(A, WL(15),B, ST(14), ST(15),C, D);
    I9 <<< 256,256,S6>>>(B, WL(16),C, ST(15), ST(16),nullptr, nullptr);
    // block 9
    I11<<< 256,256,S6>>>(C, WL(17),B, ST(16), ST(17),D, A);
    I9 <<< 256,256,S6>>>(B, WL(18),D, ST(17), ST(18),nullptr, nullptr);
    // fused final residual + pool + fc
    poolfc_k<<<NB,64>>>(D, ST(18), A, Wfc, bfc, y);
}